// round 13
// baseline (speedup 1.0000x reference)
#include <cuda_runtime.h>
#include <cuda_fp16.h>
#include <cstdint>
#include <math.h>

#define S 4096
#define D 1024
#define H 16
#define HD 64

// ---------------- device scratch -------------------------------------------
__device__ __half g_Xhi[(size_t)S * D];
__device__ __half g_Whi[4 * (size_t)D * D];
__device__ __half g_Qhi[(size_t)S * D];
__device__ __half g_Khi[(size_t)S * D];
__device__ __half g_Vhi[(size_t)S * D];
__device__ __half g_Ohi[(size_t)S * D];
__device__ float g_cos[S * 32], g_sin[S * 32];

// ---------------- helpers ---------------------------------------------------
__device__ __forceinline__ uint32_t smem_u32(const void* p) {
    uint32_t a;
    asm("{ .reg .u64 t; cvta.to.shared.u64 t, %1; cvt.u32.u64 %0, t; }"
        : "=r"(a) : "l"(p));
    return a;
}

__device__ __forceinline__ void cp16(uint32_t saddr, const void* g) {
    asm volatile("cp.async.cg.shared.global [%0], [%1], 16;" :: "r"(saddr), "l"(g));
}

__device__ __forceinline__ void ldsm4(uint32_t a, uint32_t r[4]) {
    asm volatile("ldmatrix.sync.aligned.m8n8.x4.shared.b16 {%0,%1,%2,%3}, [%4];"
                 : "=r"(r[0]), "=r"(r[1]), "=r"(r[2]), "=r"(r[3]) : "r"(a));
}

__device__ __forceinline__ void ldsm4t(uint32_t a, uint32_t r[4]) {
    asm volatile("ldmatrix.sync.aligned.m8n8.x4.trans.shared.b16 {%0,%1,%2,%3}, [%4];"
                 : "=r"(r[0]), "=r"(r[1]), "=r"(r[2]), "=r"(r[3]) : "r"(a));
}

// f32-accumulate fp16 MMA
__device__ __forceinline__ void mma16816(float c[4], const uint32_t a[4],
                                         uint32_t b0, uint32_t b1) {
    asm("mma.sync.aligned.m16n8k16.row.col.f32.f16.f16.f32 "
        "{%0,%1,%2,%3}, {%4,%5,%6,%7}, {%8,%9}, {%0,%1,%2,%3};"
        : "+f"(c[0]), "+f"(c[1]), "+f"(c[2]), "+f"(c[3])
        : "r"(a[0]), "r"(a[1]), "r"(a[2]), "r"(a[3]), "r"(b0), "r"(b1));
}

__device__ __forceinline__ uint32_t pack_h2(float a, float b) {
    __half2 h = __floats2half2_rn(a, b);
    return *(uint32_t*)&h;
}

// ---------------- conversion / rope-table kernels ---------------------------
__global__ void split_x_kernel(const float* __restrict__ x) {
    size_t i = (size_t)blockIdx.x * 256 + threadIdx.x;
    g_Xhi[i] = __float2half_rn(x[i]);
}

__global__ void split_w_kernel(const float* __restrict__ Wq, const float* __restrict__ Wk,
                               const float* __restrict__ Wv, const float* __restrict__ Wo) {
    int z = blockIdx.z;
    const float* W = (z == 0) ? Wq : (z == 1) ? Wk : (z == 2) ? Wv : Wo;
    size_t i = (size_t)blockIdx.x * 256 + threadIdx.x;
    g_Whi[(size_t)z * D * D + i] = __float2half_rn(W[i]);
}

__global__ void rope_table_kernel(const int* __restrict__ pos) {
    int m = blockIdx.x;
    int i = threadIdx.x;  // pair index 0..31
    double f = pow(10000.0, -(double)(2 * i) / 64.0);
    float ang = (float)pos[m] * (float)f;
    float sv, cv;
    sincosf(ang, &sv, &cv);
    g_cos[m * 32 + i] = cv;
    g_sin[m * 32 + i] = sv;
}

// ---------------- fp16 HMMA GEMM:  Y = A @ B^T --------------------------------
// CTA 128x128, 4 warps (2x2), each warp 64x64. k-chunk 64, double-buffered.
#define MM_SP    144                 // 128B data + 16B pad
#define MM_MAT   (128 * MM_SP)       // 18432 B
#define MM_STAGE (2 * MM_MAT)        // Ah, Bh
#define MM_SMEM  (2 * MM_STAGE)      // 73728 B

__device__ __forceinline__ void mm_load_stage(uint32_t sb, int st, int c,
                                              const __half* A_h, const __half* B_h) {
    const __half* srcs[2] = {A_h, B_h};
    int t = threadIdx.x;
#pragma unroll
    for (int i = 0; i < 16; i++) {
        int cid = t + i * 128;             // 0..2047
        int mi = cid >> 10;                // matrix 0..1 (1024 chunks each)
        int r  = (cid >> 3) & 127;         // row
        int q  = cid & 7;                  // 16B chunk within 128B row
        cp16(sb + st * MM_STAGE + mi * MM_MAT + r * MM_SP + q * 16,
             srcs[mi] + (size_t)r * D + c * 64 + q * 8);
    }
}

__device__ __forceinline__ void mm_stage_compute(uint32_t so, int wm, int wn, int lane,
                                                 float acc[4][8][4]) {
    const int lr = lane & 15, lc = lane >> 4;
#pragma unroll
    for (int ks = 0; ks < 4; ks++) {
        uint32_t a4[4][4], bh[8][2], t4[4];
#pragma unroll
        for (int i = 0; i < 4; i++)
            ldsm4(so + 0 * MM_MAT + (wm * 64 + i * 16 + lr) * MM_SP + ks * 32 + lc * 16, a4[i]);
#pragma unroll
        for (int jj = 0; jj < 4; jj++) {
            ldsm4(so + 1 * MM_MAT + (wn * 64 + jj * 16 + lr) * MM_SP + ks * 32 + lc * 16, t4);
            bh[2 * jj][0] = t4[0]; bh[2 * jj][1] = t4[2];
            bh[2 * jj + 1][0] = t4[1]; bh[2 * jj + 1][1] = t4[3];
        }
#pragma unroll
        for (int i = 0; i < 4; i++)
#pragma unroll
            for (int j = 0; j < 8; j++)
                mma16816(acc[i][j], a4[i], bh[j][0], bh[j][1]);
    }
}

// mode 1: rope + fp16 out (Q/K); 2: fp16 out (V); 3: fp32 out (final).
__device__ void mm_body(const __half* Ah, const __half* Bh,
                        int mode, float* outF, __half* outH) {
    extern __shared__ char smem[];
    uint32_t sb = smem_u32(smem);
    const int tid = threadIdx.x, lane = tid & 31, wid = tid >> 5;
    const int wm = wid >> 1, wn = wid & 1;
    const int m0 = blockIdx.y * 128, n0 = blockIdx.x * 128;

    const __half* A_h = Ah + (size_t)m0 * D;
    const __half* B_h = Bh + (size_t)n0 * D;

    float acc[4][8][4];
#pragma unroll
    for (int i = 0; i < 4; i++)
#pragma unroll
        for (int j = 0; j < 8; j++)
#pragma unroll
            for (int e = 0; e < 4; e++) acc[i][j][e] = 0.0f;

    mm_load_stage(sb, 0, 0, A_h, B_h);
    asm volatile("cp.async.commit_group;" ::: "memory");

#pragma unroll 1
    for (int c = 0; c < 16; c++) {
        int st = c & 1;
        if (c + 1 < 16) {
            mm_load_stage(sb, st ^ 1, c + 1, A_h, B_h);
            asm volatile("cp.async.commit_group;" ::: "memory");
            asm volatile("cp.async.wait_group 1;" ::: "memory");
        } else {
            asm volatile("cp.async.wait_group 0;" ::: "memory");
        }
        __syncthreads();
        mm_stage_compute(sb + st * MM_STAGE, wm, wn, lane, acc);
        __syncthreads();
    }

    const int g = lane >> 2, tig = lane & 3;
#pragma unroll
    for (int i = 0; i < 4; i++)
#pragma unroll
        for (int j = 0; j < 8; j++) {
            const int m = m0 + wm * 64 + i * 16 + g;
            const int n = n0 + wn * 64 + j * 8 + tig * 2;
#pragma unroll
            for (int rr = 0; rr < 2; rr++) {
                const int mm = m + rr * 8;
                float e = acc[i][j][rr * 2], o = acc[i][j][rr * 2 + 1];
                if (mode == 1) {
                    const int pidx = (n & 63) >> 1;
                    const float cv = g_cos[mm * 32 + pidx];
                    const float sv = g_sin[mm * 32 + pidx];
                    const float e2 = e * cv - o * sv;
                    const float o2 = e * sv + o * cv;
                    e = e2; o = o2;
                }
                if (mode == 3) {
                    *(float2*)(outF + (size_t)mm * D + n) = make_float2(e, o);
                } else {
                    *(uint32_t*)(outH + (size_t)mm * D + n) = pack_h2(e, o);
                }
            }
        }
}

__global__ __launch_bounds__(128, 2) void mm_qkv_kernel() {
    const int z = blockIdx.z;
    const __half* Bh = g_Whi + (size_t)z * D * D;
    if (z == 0)      mm_body(g_Xhi, Bh, 1, (float*)0, g_Qhi);
    else if (z == 1) mm_body(g_Xhi, Bh, 1, (float*)0, g_Khi);
    else             mm_body(g_Xhi, Bh, 2, (float*)0, g_Vhi);
}

__global__ __launch_bounds__(128, 2) void mm_out_kernel(float* __restrict__ out) {
    mm_body(g_Ohi, g_Whi + 3ull * D * D, 3, out, (__half*)0);
}

// ---------------- HMMA flash attention --------------------------------------
// CTA = 128 q rows x 1 head, 8 warps (each m16). kv tiles of 64, double-buffered.
#define AT_SP    144
#define AT_MAT   (64 * AT_SP)              // 9216 B (one 64-row matrix)
#define AT_QBYTES (128 * AT_SP)            // 18432 B (128-row Q)
#define AT_KVOFF AT_QBYTES
#define AT_STAGE (2 * AT_MAT)              // Kh, Vh per stage
#define AT_SMEM  (AT_KVOFF + 2 * AT_STAGE) // 55296 B

// load one 64-row x 128B matrix with 256 threads (2 chunks each)
__device__ __forceinline__ void at_load64(uint32_t sdst, const __half* g) {
    int t = threadIdx.x;
#pragma unroll
    for (int i = 0; i < 2; i++) {
        int cid = t + i * 256;      // 0..511
        int r = cid >> 3;
        int q = cid & 7;
        cp16(sdst + r * AT_SP + q * 16, g + (size_t)r * D + q * 8);
    }
}

// load 128-row Q with 256 threads (4 chunks each)
__device__ __forceinline__ void at_load_q(uint32_t sdst, const __half* g) {
    int t = threadIdx.x;
#pragma unroll
    for (int i = 0; i < 4; i++) {
        int cid = t + i * 256;      // 0..1023
        int r = cid >> 3;           // 0..127
        int q = cid & 7;
        cp16(sdst + r * AT_SP + q * 16, g + (size_t)r * D + q * 8);
    }
}

__global__ __launch_bounds__(256) void attn_kernel() {
    extern __shared__ char smem[];
    uint32_t sb = smem_u32(smem);
    const int tid = threadIdx.x, lane = tid & 31, w = tid >> 5;  // w: 0..7
    const int qt = (int)gridDim.x - 1 - (int)blockIdx.x;         // heavy first
    const int h = blockIdx.y;
    const int qbase = qt * 128;
    const int lr = lane & 15, lc = lane >> 4;
    const int g = lane >> 2, tig = lane & 3;

    // Q + KV tile 0 into stage 0
    at_load_q(sb, g_Qhi + (size_t)qbase * D + h * HD);
    at_load64(sb + AT_KVOFF + 0 * AT_MAT, g_Khi + (size_t)h * HD);
    at_load64(sb + AT_KVOFF + 1 * AT_MAT, g_Vhi + (size_t)h * HD);
    asm volatile("cp.async.commit_group;" ::: "memory");

    uint32_t qh[4][4];
    bool qloaded = false;

    float o[8][4];
#pragma unroll
    for (int j = 0; j < 8; j++)
#pragma unroll
        for (int e = 0; e < 4; e++) o[j][e] = 0.0f;
    float m0r = -1e30f, m1r = -1e30f, l0 = 0.0f, l1 = 0.0f;

    const int nt = 2 * qt + 2;

#pragma unroll 1
    for (int kt = 0; kt < nt; kt++) {
        if (kt + 1 < nt) {
            const size_t nkoff = (size_t)((kt + 1) * 64) * D + h * HD;
            const uint32_t nb = sb + AT_KVOFF + ((kt + 1) & 1) * AT_STAGE;
            at_load64(nb + 0 * AT_MAT, g_Khi + nkoff);
            at_load64(nb + 1 * AT_MAT, g_Vhi + nkoff);
            asm volatile("cp.async.commit_group;" ::: "memory");
            asm volatile("cp.async.wait_group 1;" ::: "memory");
        } else {
            asm volatile("cp.async.wait_group 0;" ::: "memory");
        }
        __syncthreads();

        if (!qloaded) {
            qloaded = true;
#pragma unroll
            for (int ks = 0; ks < 4; ks++)
                ldsm4(sb + (w * 16 + lr) * AT_SP + ks * 32 + lc * 16, qh[ks]);
        }

        const uint32_t kb = sb + AT_KVOFF + (kt & 1) * AT_STAGE;
        const uint32_t sK = kb, sV = kb + AT_MAT;

        float s[8][4];
#pragma unroll
        for (int j = 0; j < 8; j++)
#pragma unroll
            for (int e = 0; e < 4; e++) s[j][e] = 0.0f;

        // --- S = Qh*Kh^T (f32) ---
#pragma unroll
        for (int ks = 0; ks < 4; ks++) {
            uint32_t kh[4][4];
#pragma unroll
            for (int jj = 0; jj < 4; jj++)
                ldsm4(sK + (jj * 16 + lr) * AT_SP + ks * 32 + lc * 16, kh[jj]);
#pragma unroll
            for (int jj = 0; jj < 4; jj++) {
                mma16816(s[2 * jj],     qh[ks], kh[jj][0], kh[jj][2]);
                mma16816(s[2 * jj + 1], qh[ks], kh[jj][1], kh[jj][3]);
            }
        }

        // --- scale + causal mask (warp-dependent) ---
        const bool diag = (kt * 64 + 63) > (qbase + w * 16);
#pragma unroll
        for (int j = 0; j < 8; j++)
#pragma unroll
            for (int e = 0; e < 4; e++) {
                float v = s[j][e] * 0.125f;
                if (diag) {
                    const int kvc = kt * 64 + j * 8 + tig * 2 + (e & 1);
                    const int qr  = qbase + w * 16 + g + ((e >> 1) << 3);
                    if (kvc > qr) v = -1e30f;
                }
                s[j][e] = v;
            }

        // --- online softmax ---
        float mx0 = -1e30f, mx1 = -1e30f;
#pragma unroll
        for (int j = 0; j < 8; j++) {
            mx0 = fmaxf(mx0, fmaxf(s[j][0], s[j][1]));
            mx1 = fmaxf(mx1, fmaxf(s[j][2], s[j][3]));
        }
        mx0 = fmaxf(mx0, __shfl_xor_sync(0xffffffffu, mx0, 1));
        mx0 = fmaxf(mx0, __shfl_xor_sync(0xffffffffu, mx0, 2));
        mx1 = fmaxf(mx1, __shfl_xor_sync(0xffffffffu, mx1, 1));
        mx1 = fmaxf(mx1, __shfl_xor_sync(0xffffffffu, mx1, 2));
        const float nm0 = fmaxf(m0r, mx0), nm1 = fmaxf(m1r, mx1);
        const float sc0 = __expf(m0r - nm0), sc1 = __expf(m1r - nm1);
        m0r = nm0; m1r = nm1;
        l0 *= sc0; l1 *= sc1;
#pragma unroll
        for (int j = 0; j < 8; j++) {
            o[j][0] *= sc0; o[j][1] *= sc0;
            o[j][2] *= sc1; o[j][3] *= sc1;
        }
#pragma unroll
        for (int j = 0; j < 8; j++) {
            s[j][0] = __expf(s[j][0] - nm0); s[j][1] = __expf(s[j][1] - nm0);
            s[j][2] = __expf(s[j][2] - nm1); s[j][3] = __expf(s[j][3] - nm1);
            l0 += s[j][0] + s[j][1];
            l1 += s[j][2] + s[j][3];
        }

        // --- O += Ph*Vh (f32) ---
#pragma unroll
        for (int ks = 0; ks < 4; ks++) {
            uint32_t pa[4];
#pragma unroll
            for (int hv = 0; hv < 2; hv++) {
                pa[2 * hv]     = pack_h2(s[2 * ks + hv][0], s[2 * ks + hv][1]);
                pa[2 * hv + 1] = pack_h2(s[2 * ks + hv][2], s[2 * ks + hv][3]);
            }
            uint32_t vh[4][4];
#pragma unroll
            for (int jj = 0; jj < 4; jj++)
                ldsm4t(sV + (ks * 16 + lr) * AT_SP + jj * 32 + lc * 16, vh[jj]);
#pragma unroll
            for (int jj = 0; jj < 4; jj++) {
                mma16816(o[2 * jj],     pa, vh[jj][0], vh[jj][1]);
                mma16816(o[2 * jj + 1], pa, vh[jj][2], vh[jj][3]);
            }
        }
        __syncthreads();   // all warps done with this stage before it is overwritten
    }

    // --- finalize ---
    l0 += __shfl_xor_sync(0xffffffffu, l0, 1);
    l0 += __shfl_xor_sync(0xffffffffu, l0, 2);
    l1 += __shfl_xor_sync(0xffffffffu, l1, 1);
    l1 += __shfl_xor_sync(0xffffffffu, l1, 2);
    const float i0 = 1.0f / l0, i1 = 1.0f / l1;

#pragma unroll
    for (int j = 0; j < 8; j++) {
        const int n = h * HD + j * 8 + tig * 2;
#pragma unroll
        for (int rr = 0; rr < 2; rr++) {
            const int mm = qbase + w * 16 + g + rr * 8;
            const float inv = rr ? i1 : i0;
            *(uint32_t*)(g_Ohi + (size_t)mm * D + n) =
                pack_h2(o[j][2 * rr] * inv, o[j][2 * rr + 1] * inv);
        }
    }
}

// ---------------------------------------------------------------------------
extern "C" void kernel_launch(void* const* d_in, const int* in_sizes, int n_in,
                              void* d_out, int out_size) {
    (void)in_sizes; (void)n_in; (void)out_size;
    const float* x   = (const float*)d_in[0];
    const int*   pos = (const int*)  d_in[1];
    const float* Wq  = (const float*)d_in[2];
    const float* Wk  = (const float*)d_in[3];
    const float* Wv  = (const float*)d_in[4];
    const float* Wo  = (const float*)d_in[5];
    float* out = (float*)d_out;

    cudaFuncSetAttribute(mm_qkv_kernel, cudaFuncAttributeMaxDynamicSharedMemorySize, MM_SMEM);
    cudaFuncSetAttribute(mm_out_kernel, cudaFuncAttributeMaxDynamicSharedMemorySize, MM_SMEM);
    cudaFuncSetAttribute(attn_kernel, cudaFuncAttributeMaxDynamicSharedMemorySize, AT_SMEM);

    split_x_kernel<<<(S * D) / 256, 256>>>(x);
    split_w_kernel<<<dim3((D * D) / 256, 1, 4), 256>>>(Wq, Wk, Wv, Wo);
    rope_table_kernel<<<S, 32>>>(pos);

    mm_qkv_kernel<<<dim3(D / 128, S / 128, 3), 128, MM_SMEM>>>();
    attn_kernel<<<dim3(S / 128, H), 256, AT_SMEM>>>();
    mm_out_kernel<<<dim3(D / 128, S / 128, 1), 128, MM_SMEM>>>(out);
}

// round 14
// speedup vs baseline: 1.0735x; 1.0735x over previous
#include <cuda_runtime.h>
#include <cuda_fp16.h>
#include <cstdint>
#include <math.h>

#define S 4096
#define D 1024
#define H 16
#define HD 64
#define SCALE_LOG2E 0.1803368801111204f   // 0.125 * log2(e)

// ---------------- device scratch -------------------------------------------
__device__ __half g_Xhi[(size_t)S * D];
__device__ __half g_Whi[4 * (size_t)D * D];
__device__ __half g_Qhi[(size_t)S * D];
__device__ __half g_Khi[(size_t)S * D];
__device__ __half g_Vhi[(size_t)S * D];
__device__ __half g_Ohi[(size_t)S * D];
__device__ float g_cos[S * 32], g_sin[S * 32];

// ---------------- helpers ---------------------------------------------------
__device__ __forceinline__ uint32_t smem_u32(const void* p) {
    uint32_t a;
    asm("{ .reg .u64 t; cvta.to.shared.u64 t, %1; cvt.u32.u64 %0, t; }"
        : "=r"(a) : "l"(p));
    return a;
}

__device__ __forceinline__ void cp16(uint32_t saddr, const void* g) {
    asm volatile("cp.async.cg.shared.global [%0], [%1], 16;" :: "r"(saddr), "l"(g));
}

__device__ __forceinline__ void ldsm4(uint32_t a, uint32_t r[4]) {
    asm volatile("ldmatrix.sync.aligned.m8n8.x4.shared.b16 {%0,%1,%2,%3}, [%4];"
                 : "=r"(r[0]), "=r"(r[1]), "=r"(r[2]), "=r"(r[3]) : "r"(a));
}

__device__ __forceinline__ void ldsm4t(uint32_t a, uint32_t r[4]) {
    asm volatile("ldmatrix.sync.aligned.m8n8.x4.trans.shared.b16 {%0,%1,%2,%3}, [%4];"
                 : "=r"(r[0]), "=r"(r[1]), "=r"(r[2]), "=r"(r[3]) : "r"(a));
}

// f32-accumulate fp16 MMA
__device__ __forceinline__ void mma16816(float c[4], const uint32_t a[4],
                                         uint32_t b0, uint32_t b1) {
    asm("mma.sync.aligned.m16n8k16.row.col.f32.f16.f16.f32 "
        "{%0,%1,%2,%3}, {%4,%5,%6,%7}, {%8,%9}, {%0,%1,%2,%3};"
        : "+f"(c[0]), "+f"(c[1]), "+f"(c[2]), "+f"(c[3])
        : "r"(a[0]), "r"(a[1]), "r"(a[2]), "r"(a[3]), "r"(b0), "r"(b1));
}

__device__ __forceinline__ uint32_t pack_h2(float a, float b) {
    __half2 h = __floats2half2_rn(a, b);
    return *(uint32_t*)&h;
}

// raw ex2.approx — input already in log2 domain
__device__ __forceinline__ float ex2(float x) {
    float r;
    asm("ex2.approx.f32 %0, %1;" : "=f"(r) : "f"(x));
    return r;
}

// ---------------- conversion / rope-table kernels ---------------------------
__global__ void split_x_kernel(const float* __restrict__ x) {
    size_t i = (size_t)blockIdx.x * 256 + threadIdx.x;
    g_Xhi[i] = __float2half_rn(x[i]);
}

__global__ void split_w_kernel(const float* __restrict__ Wq, const float* __restrict__ Wk,
                               const float* __restrict__ Wv, const float* __restrict__ Wo) {
    int z = blockIdx.z;
    const float* W = (z == 0) ? Wq : (z == 1) ? Wk : (z == 2) ? Wv : Wo;
    size_t i = (size_t)blockIdx.x * 256 + threadIdx.x;
    g_Whi[(size_t)z * D * D + i] = __float2half_rn(W[i]);
}

__global__ void rope_table_kernel(const int* __restrict__ pos) {
    int m = blockIdx.x;
    int i = threadIdx.x;  // pair index 0..31
    double f = pow(10000.0, -(double)(2 * i) / 64.0);
    float ang = (float)pos[m] * (float)f;
    float sv, cv;
    sincosf(ang, &sv, &cv);
    g_cos[m * 32 + i] = cv;
    g_sin[m * 32 + i] = sv;
}

// ---------------- fp16 HMMA GEMM:  Y = A @ B^T --------------------------------
// CTA 128x128, 4 warps (2x2), each warp 64x64. k-chunk 64, double-buffered.
#define MM_SP    144                 // 128B data + 16B pad
#define MM_MAT   (128 * MM_SP)       // 18432 B
#define MM_STAGE (2 * MM_MAT)        // Ah, Bh
#define MM_SMEM  (2 * MM_STAGE)      // 73728 B

__device__ __forceinline__ void mm_load_stage(uint32_t sb, int st, int c,
                                              const __half* A_h, const __half* B_h) {
    const __half* srcs[2] = {A_h, B_h};
    int t = threadIdx.x;
#pragma unroll
    for (int i = 0; i < 16; i++) {
        int cid = t + i * 128;             // 0..2047
        int mi = cid >> 10;                // matrix 0..1
        int r  = (cid >> 3) & 127;         // row
        int q  = cid & 7;                  // 16B chunk within 128B row
        cp16(sb + st * MM_STAGE + mi * MM_MAT + r * MM_SP + q * 16,
             srcs[mi] + (size_t)r * D + c * 64 + q * 8);
    }
}

__device__ __forceinline__ void mm_stage_compute(uint32_t so, int wm, int wn, int lane,
                                                 float acc[4][8][4]) {
    const int lr = lane & 15, lc = lane >> 4;
#pragma unroll
    for (int ks = 0; ks < 4; ks++) {
        uint32_t a4[4][4], bh[8][2], t4[4];
#pragma unroll
        for (int i = 0; i < 4; i++)
            ldsm4(so + 0 * MM_MAT + (wm * 64 + i * 16 + lr) * MM_SP + ks * 32 + lc * 16, a4[i]);
#pragma unroll
        for (int jj = 0; jj < 4; jj++) {
            ldsm4(so + 1 * MM_MAT + (wn * 64 + jj * 16 + lr) * MM_SP + ks * 32 + lc * 16, t4);
            bh[2 * jj][0] = t4[0]; bh[2 * jj][1] = t4[2];
            bh[2 * jj + 1][0] = t4[1]; bh[2 * jj + 1][1] = t4[3];
        }
#pragma unroll
        for (int i = 0; i < 4; i++)
#pragma unroll
            for (int j = 0; j < 8; j++)
                mma16816(acc[i][j], a4[i], bh[j][0], bh[j][1]);
    }
}

// mode 1: rope + fp16 out (Q/K); 2: fp16 out (V); 3: fp32 out (final).
__device__ void mm_body(const __half* Ah, const __half* Bh,
                        int mode, float* outF, __half* outH) {
    extern __shared__ char smem[];
    uint32_t sb = smem_u32(smem);
    const int tid = threadIdx.x, lane = tid & 31, wid = tid >> 5;
    const int wm = wid >> 1, wn = wid & 1;
    const int m0 = blockIdx.y * 128, n0 = blockIdx.x * 128;

    const __half* A_h = Ah + (size_t)m0 * D;
    const __half* B_h = Bh + (size_t)n0 * D;

    float acc[4][8][4];
#pragma unroll
    for (int i = 0; i < 4; i++)
#pragma unroll
        for (int j = 0; j < 8; j++)
#pragma unroll
            for (int e = 0; e < 4; e++) acc[i][j][e] = 0.0f;

    mm_load_stage(sb, 0, 0, A_h, B_h);
    asm volatile("cp.async.commit_group;" ::: "memory");

#pragma unroll 1
    for (int c = 0; c < 16; c++) {
        int st = c & 1;
        if (c + 1 < 16) {
            mm_load_stage(sb, st ^ 1, c + 1, A_h, B_h);
            asm volatile("cp.async.commit_group;" ::: "memory");
            asm volatile("cp.async.wait_group 1;" ::: "memory");
        } else {
            asm volatile("cp.async.wait_group 0;" ::: "memory");
        }
        __syncthreads();
        mm_stage_compute(sb + st * MM_STAGE, wm, wn, lane, acc);
        __syncthreads();
    }

    const int g = lane >> 2, tig = lane & 3;
#pragma unroll
    for (int i = 0; i < 4; i++)
#pragma unroll
        for (int j = 0; j < 8; j++) {
            const int m = m0 + wm * 64 + i * 16 + g;
            const int n = n0 + wn * 64 + j * 8 + tig * 2;
#pragma unroll
            for (int rr = 0; rr < 2; rr++) {
                const int mm = m + rr * 8;
                float e = acc[i][j][rr * 2], o = acc[i][j][rr * 2 + 1];
                if (mode == 1) {
                    const int pidx = (n & 63) >> 1;
                    const float cv = g_cos[mm * 32 + pidx];
                    const float sv = g_sin[mm * 32 + pidx];
                    const float e2 = e * cv - o * sv;
                    const float o2 = e * sv + o * cv;
                    e = e2; o = o2;
                }
                if (mode == 3) {
                    *(float2*)(outF + (size_t)mm * D + n) = make_float2(e, o);
                } else {
                    *(uint32_t*)(outH + (size_t)mm * D + n) = pack_h2(e, o);
                }
            }
        }
}

__global__ __launch_bounds__(128, 2) void mm_qkv_kernel() {
    const int z = blockIdx.z;
    const __half* Bh = g_Whi + (size_t)z * D * D;
    if (z == 0)      mm_body(g_Xhi, Bh, 1, (float*)0, g_Qhi);
    else if (z == 1) mm_body(g_Xhi, Bh, 1, (float*)0, g_Khi);
    else             mm_body(g_Xhi, Bh, 2, (float*)0, g_Vhi);
}

__global__ __launch_bounds__(128, 2) void mm_out_kernel(float* __restrict__ out) {
    mm_body(g_Ohi, g_Whi + 3ull * D * D, 3, out, (__half*)0);
}

// ---------------- HMMA flash attention --------------------------------------
// CTA = 64 q rows x 1 head, 4 warps. kv tiles of 64, double-buffered.
// Scores pre-scaled into log2 domain (SCALE_LOG2E); exps via raw ex2.approx.
#define AT_SP    144
#define AT_MAT   (64 * AT_SP)
#define AT_KVOFF (1 * AT_MAT)          // after Qh
#define AT_STAGE (2 * AT_MAT)          // Kh, Vh per stage
#define AT_SMEM  (AT_KVOFF + 2 * AT_STAGE)   // 46080 B

__device__ __forceinline__ void at_load64(uint32_t sdst, const __half* g) {
    int t = threadIdx.x;
#pragma unroll
    for (int i = 0; i < 4; i++) {
        int cid = t + i * 128;
        int r = cid >> 3;
        int q = cid & 7;
        cp16(sdst + r * AT_SP + q * 16, g + (size_t)r * D + q * 8);
    }
}

__global__ __launch_bounds__(128, 3) void attn_kernel() {
    extern __shared__ char smem[];
    uint32_t sb = smem_u32(smem);
    const int tid = threadIdx.x, lane = tid & 31, w = tid >> 5;
    const int qt = (int)gridDim.x - 1 - (int)blockIdx.x;   // heavy first
    const int h = blockIdx.y;
    const int qbase = qt * 64;
    const int lr = lane & 15, lc = lane >> 4;
    const int g = lane >> 2, tig = lane & 3;

    // Q + KV tile 0 into stage 0
    at_load64(sb, g_Qhi + (size_t)qbase * D + h * HD);
    at_load64(sb + AT_KVOFF + 0 * AT_MAT, g_Khi + (size_t)h * HD);
    at_load64(sb + AT_KVOFF + 1 * AT_MAT, g_Vhi + (size_t)h * HD);
    asm volatile("cp.async.commit_group;" ::: "memory");

    uint32_t qh[4][4];
    bool qloaded = false;

    float o[8][4];
#pragma unroll
    for (int j = 0; j < 8; j++)
#pragma unroll
        for (int e = 0; e < 4; e++) o[j][e] = 0.0f;
    float m0r = -1e30f, m1r = -1e30f, l0 = 0.0f, l1 = 0.0f;

#pragma unroll 1
    for (int kt = 0; kt <= qt; kt++) {
        if (kt < qt) {
            const size_t nkoff = (size_t)((kt + 1) * 64) * D + h * HD;
            const uint32_t nb = sb + AT_KVOFF + ((kt + 1) & 1) * AT_STAGE;
            at_load64(nb + 0 * AT_MAT, g_Khi + nkoff);
            at_load64(nb + 1 * AT_MAT, g_Vhi + nkoff);
            asm volatile("cp.async.commit_group;" ::: "memory");
            asm volatile("cp.async.wait_group 1;" ::: "memory");
        } else {
            asm volatile("cp.async.wait_group 0;" ::: "memory");
        }
        __syncthreads();

        if (!qloaded) {
            qloaded = true;
#pragma unroll
            for (int ks = 0; ks < 4; ks++)
                ldsm4(sb + (w * 16 + lr) * AT_SP + ks * 32 + lc * 16, qh[ks]);
        }

        const uint32_t kb = sb + AT_KVOFF + (kt & 1) * AT_STAGE;
        const uint32_t sK = kb, sV = kb + AT_MAT;

        float s[8][4];
#pragma unroll
        for (int j = 0; j < 8; j++)
#pragma unroll
            for (int e = 0; e < 4; e++) s[j][e] = 0.0f;

        // --- S = Qh*Kh^T (f32) ---
#pragma unroll
        for (int ks = 0; ks < 4; ks++) {
            uint32_t kh[4][4];
#pragma unroll
            for (int jj = 0; jj < 4; jj++)
                ldsm4(sK + (jj * 16 + lr) * AT_SP + ks * 32 + lc * 16, kh[jj]);
#pragma unroll
            for (int jj = 0; jj < 4; jj++) {
                mma16816(s[2 * jj],     qh[ks], kh[jj][0], kh[jj][2]);
                mma16816(s[2 * jj + 1], qh[ks], kh[jj][1], kh[jj][3]);
            }
        }

        // --- scale into log2 domain + causal mask ---
        const bool diag = (kt == qt);
#pragma unroll
        for (int j = 0; j < 8; j++)
#pragma unroll
            for (int e = 0; e < 4; e++) {
                float v = s[j][e] * SCALE_LOG2E;
                if (diag) {
                    const int kvc = kt * 64 + j * 8 + tig * 2 + (e & 1);
                    const int qr  = qbase + w * 16 + g + ((e >> 1) << 3);
                    if (kvc > qr) v = -1e30f;
                }
                s[j][e] = v;
            }

        // --- online softmax (log2 domain) ---
        float mx0 = -1e30f, mx1 = -1e30f;
#pragma unroll
        for (int j = 0; j < 8; j++) {
            mx0 = fmaxf(mx0, fmaxf(s[j][0], s[j][1]));
            mx1 = fmaxf(mx1, fmaxf(s[j][2], s[j][3]));
        }
        mx0 = fmaxf(mx0, __shfl_xor_sync(0xffffffffu, mx0, 1));
        mx0 = fmaxf(mx0, __shfl_xor_sync(0xffffffffu, mx0, 2));
        mx1 = fmaxf(mx1, __shfl_xor_sync(0xffffffffu, mx1, 1));
        mx1 = fmaxf(mx1, __shfl_xor_sync(0xffffffffu, mx1, 2));
        const float nm0 = fmaxf(m0r, mx0), nm1 = fmaxf(m1r, mx1);
        const float sc0 = ex2(m0r - nm0), sc1 = ex2(m1r - nm1);
        m0r = nm0; m1r = nm1;
        l0 *= sc0; l1 *= sc1;
#pragma unroll
        for (int j = 0; j < 8; j++) {
            o[j][0] *= sc0; o[j][1] *= sc0;
            o[j][2] *= sc1; o[j][3] *= sc1;
        }
#pragma unroll
        for (int j = 0; j < 8; j++) {
            s[j][0] = ex2(s[j][0] - nm0); s[j][1] = ex2(s[j][1] - nm0);
            s[j][2] = ex2(s[j][2] - nm1); s[j][3] = ex2(s[j][3] - nm1);
            l0 += s[j][0] + s[j][1];
            l1 += s[j][2] + s[j][3];
        }

        // --- O += Ph*Vh (f32) ---
#pragma unroll
        for (int ks = 0; ks < 4; ks++) {
            uint32_t pa[4];
#pragma unroll
            for (int hv = 0; hv < 2; hv++) {
                pa[2 * hv]     = pack_h2(s[2 * ks + hv][0], s[2 * ks + hv][1]);
                pa[2 * hv + 1] = pack_h2(s[2 * ks + hv][2], s[2 * ks + hv][3]);
            }
            uint32_t vh[4][4];
#pragma unroll
            for (int jj = 0; jj < 4; jj++)
                ldsm4t(sV + (ks * 16 + lr) * AT_SP + jj * 32 + lc * 16, vh[jj]);
#pragma unroll
            for (int jj = 0; jj < 4; jj++) {
                mma16816(o[2 * jj],     pa, vh[jj][0], vh[jj][1]);
                mma16816(o[2 * jj + 1], pa, vh[jj][2], vh[jj][3]);
            }
        }
        __syncthreads();   // all warps done with this stage before it is overwritten
    }

    // --- finalize ---
    l0 += __shfl_xor_sync(0xffffffffu, l0, 1);
    l0 += __shfl_xor_sync(0xffffffffu, l0, 2);
    l1 += __shfl_xor_sync(0xffffffffu, l1, 1);
    l1 += __shfl_xor_sync(0xffffffffu, l1, 2);
    const float i0 = 1.0f / l0, i1 = 1.0f / l1;

#pragma unroll
    for (int j = 0; j < 8; j++) {
        const int n = h * HD + j * 8 + tig * 2;
#pragma unroll
        for (int rr = 0; rr < 2; rr++) {
            const int mm = qbase + w * 16 + g + rr * 8;
            const float inv = rr ? i1 : i0;
            *(uint32_t*)(g_Ohi + (size_t)mm * D + n) =
                pack_h2(o[j][2 * rr] * inv, o[j][2 * rr + 1] * inv);
        }
    }
}

// ---------------------------------------------------------------------------
extern "C" void kernel_launch(void* const* d_in, const int* in_sizes, int n_in,
                              void* d_out, int out_size) {
    (void)in_sizes; (void)n_in; (void)out_size;
    const float* x   = (const float*)d_in[0];
    const int*   pos = (const int*)  d_in[1];
    const float* Wq  = (const float*)d_in[2];
    const float* Wk  = (const float*)d_in[3];
    const float* Wv  = (const float*)d_in[4];
    const float* Wo  = (const float*)d_in[5];
    float* out = (float*)d_out;

    cudaFuncSetAttribute(mm_qkv_kernel, cudaFuncAttributeMaxDynamicSharedMemorySize, MM_SMEM);
    cudaFuncSetAttribute(mm_out_kernel, cudaFuncAttributeMaxDynamicSharedMemorySize, MM_SMEM);
    cudaFuncSetAttribute(attn_kernel, cudaFuncAttributeMaxDynamicSharedMemorySize, AT_SMEM);

    split_x_kernel<<<(S * D) / 256, 256>>>(x);
    split_w_kernel<<<dim3((D * D) / 256, 1, 4), 256>>>(Wq, Wk, Wv, Wo);
    rope_table_kernel<<<S, 32>>>(pos);

    mm_qkv_kernel<<<dim3(D / 128, S / 128, 3), 128, MM_SMEM>>>();
    attn_kernel<<<dim3(S / 64, H), 128, AT_SMEM>>>();
    mm_out_kernel<<<dim3(D / 128, S / 128, 1), 128, MM_SMEM>>>(out);
}

// round 15
// speedup vs baseline: 1.1254x; 1.0483x over previous
#include <cuda_runtime.h>
#include <cuda_fp16.h>
#include <cstdint>
#include <math.h>

#define S 4096
#define D 1024
#define H 16
#define HD 64
#define SCALE_LOG2E 0.1803368801111204f   // 0.125 * log2(e)

// ---------------- device scratch -------------------------------------------
__device__ __half g_Xhi[(size_t)S * D];
__device__ __half g_Whi[4 * (size_t)D * D];
__device__ __half g_Qhi[(size_t)S * D];
__device__ __half g_Khi[(size_t)S * D];
__device__ __half g_Vhi[(size_t)S * D];
__device__ __half g_Ohi[(size_t)S * D];
__device__ float g_cos[S * 32], g_sin[S * 32];

// ---------------- helpers ---------------------------------------------------
__device__ __forceinline__ uint32_t smem_u32(const void* p) {
    uint32_t a;
    asm("{ .reg .u64 t; cvta.to.shared.u64 t, %1; cvt.u32.u64 %0, t; }"
        : "=r"(a) : "l"(p));
    return a;
}

__device__ __forceinline__ void cp16(uint32_t saddr, const void* g) {
    asm volatile("cp.async.cg.shared.global [%0], [%1], 16;" :: "r"(saddr), "l"(g));
}

__device__ __forceinline__ void ldsm4(uint32_t a, uint32_t r[4]) {
    asm volatile("ldmatrix.sync.aligned.m8n8.x4.shared.b16 {%0,%1,%2,%3}, [%4];"
                 : "=r"(r[0]), "=r"(r[1]), "=r"(r[2]), "=r"(r[3]) : "r"(a));
}

__device__ __forceinline__ void ldsm4t(uint32_t a, uint32_t r[4]) {
    asm volatile("ldmatrix.sync.aligned.m8n8.x4.trans.shared.b16 {%0,%1,%2,%3}, [%4];"
                 : "=r"(r[0]), "=r"(r[1]), "=r"(r[2]), "=r"(r[3]) : "r"(a));
}

// f32-accumulate fp16 MMA
__device__ __forceinline__ void mma16816(float c[4], const uint32_t a[4],
                                         uint32_t b0, uint32_t b1) {
    asm("mma.sync.aligned.m16n8k16.row.col.f32.f16.f16.f32 "
        "{%0,%1,%2,%3}, {%4,%5,%6,%7}, {%8,%9}, {%0,%1,%2,%3};"
        : "+f"(c[0]), "+f"(c[1]), "+f"(c[2]), "+f"(c[3])
        : "r"(a[0]), "r"(a[1]), "r"(a[2]), "r"(a[3]), "r"(b0), "r"(b1));
}

__device__ __forceinline__ uint32_t pack_h2(float a, float b) {
    __half2 h = __floats2half2_rn(a, b);
    return *(uint32_t*)&h;
}

__device__ __forceinline__ float ex2(float x) {
    float r;
    asm("ex2.approx.f32 %0, %1;" : "=f"(r) : "f"(x));
    return r;
}

// ---------------- fused prep kernel (x-convert + W-convert + rope) ----------
// grid = 16384 blocks x 256 threads. x: S*D = 4M elems; W: 4*D*D = 4M elems.
__global__ void prep_kernel(const float* __restrict__ x, const int* __restrict__ pos,
                            const float* __restrict__ Wq, const float* __restrict__ Wk,
                            const float* __restrict__ Wv, const float* __restrict__ Wo) {
    size_t i = (size_t)blockIdx.x * 256 + threadIdx.x;
    g_Xhi[i] = __float2half_rn(x[i]);
    // W: i spans [0, 4*D*D)
    size_t wcap = (size_t)D * D;
    const float* W = (i < wcap) ? Wq : (i < 2 * wcap) ? Wk : (i < 3 * wcap) ? Wv : Wo;
    g_Whi[i] = __float2half_rn(W[i & (wcap - 1)]);
    // rope table: first S blocks, first 32 threads
    if (blockIdx.x < S && threadIdx.x < 32) {
        int m = blockIdx.x, k = threadIdx.x;
        double f = pow(10000.0, -(double)(2 * k) / 64.0);
        float ang = (float)pos[m] * (float)f;
        float sv, cv;
        sincosf(ang, &sv, &cv);
        g_cos[m * 32 + k] = cv;
        g_sin[m * 32 + k] = sv;
    }
}

// ---------------- fp16 HMMA GEMM:  Y = A @ B^T --------------------------------
// CTA 128x128, 4 warps (2x2), each warp 64x64. k-chunk 64, double-buffered,
// single barrier per k-iteration (issue-after-barrier pipeline).
#define MM_SP    144                 // 128B data + 16B pad
#define MM_MAT   (128 * MM_SP)       // 18432 B
#define MM_STAGE (2 * MM_MAT)        // Ah, Bh
#define MM_SMEM  (2 * MM_STAGE)      // 73728 B

__device__ __forceinline__ void mm_load_stage(uint32_t sb, int st, int c,
                                              const __half* A_h, const __half* B_h) {
    const __half* srcs[2] = {A_h, B_h};
    int t = threadIdx.x;
#pragma unroll
    for (int i = 0; i < 16; i++) {
        int cid = t + i * 128;             // 0..2047
        int mi = cid >> 10;                // matrix 0..1
        int r  = (cid >> 3) & 127;         // row
        int q  = cid & 7;                  // 16B chunk within 128B row
        cp16(sb + st * MM_STAGE + mi * MM_MAT + r * MM_SP + q * 16,
             srcs[mi] + (size_t)r * D + c * 64 + q * 8);
    }
}

__device__ __forceinline__ void mm_stage_compute(uint32_t so, int wm, int wn, int lane,
                                                 float acc[4][8][4]) {
    const int lr = lane & 15, lc = lane >> 4;
#pragma unroll
    for (int ks = 0; ks < 4; ks++) {
        uint32_t a4[4][4], bh[8][2], t4[4];
#pragma unroll
        for (int i = 0; i < 4; i++)
            ldsm4(so + 0 * MM_MAT + (wm * 64 + i * 16 + lr) * MM_SP + ks * 32 + lc * 16, a4[i]);
#pragma unroll
        for (int jj = 0; jj < 4; jj++) {
            ldsm4(so + 1 * MM_MAT + (wn * 64 + jj * 16 + lr) * MM_SP + ks * 32 + lc * 16, t4);
            bh[2 * jj][0] = t4[0]; bh[2 * jj][1] = t4[2];
            bh[2 * jj + 1][0] = t4[1]; bh[2 * jj + 1][1] = t4[3];
        }
#pragma unroll
        for (int i = 0; i < 4; i++)
#pragma unroll
            for (int j = 0; j < 8; j++)
                mma16816(acc[i][j], a4[i], bh[j][0], bh[j][1]);
    }
}

// mode 1: rope + fp16 out (Q/K); 2: fp16 out (V); 3: fp32 out (final).
__device__ void mm_body(const __half* Ah, const __half* Bh,
                        int mode, float* outF, __half* outH) {
    extern __shared__ char smem[];
    uint32_t sb = smem_u32(smem);
    const int tid = threadIdx.x, lane = tid & 31, wid = tid >> 5;
    const int wm = wid >> 1, wn = wid & 1;
    const int m0 = blockIdx.y * 128, n0 = blockIdx.x * 128;

    const __half* A_h = Ah + (size_t)m0 * D;
    const __half* B_h = Bh + (size_t)n0 * D;

    float acc[4][8][4];
#pragma unroll
    for (int i = 0; i < 4; i++)
#pragma unroll
        for (int j = 0; j < 8; j++)
#pragma unroll
            for (int e = 0; e < 4; e++) acc[i][j][e] = 0.0f;

    mm_load_stage(sb, 0, 0, A_h, B_h);
    asm volatile("cp.async.commit_group;" ::: "memory");

#pragma unroll 1
    for (int c = 0; c < 16; c++) {
        int st = c & 1;
        asm volatile("cp.async.wait_group 0;" ::: "memory");
        __syncthreads();
        if (c + 1 < 16) {
            mm_load_stage(sb, st ^ 1, c + 1, A_h, B_h);
            asm volatile("cp.async.commit_group;" ::: "memory");
        }
        mm_stage_compute(sb + st * MM_STAGE, wm, wn, lane, acc);
    }

    const int g = lane >> 2, tig = lane & 3;
#pragma unroll
    for (int i = 0; i < 4; i++)
#pragma unroll
        for (int j = 0; j < 8; j++) {
            const int m = m0 + wm * 64 + i * 16 + g;
            const int n = n0 + wn * 64 + j * 8 + tig * 2;
#pragma unroll
            for (int rr = 0; rr < 2; rr++) {
                const int mm = m + rr * 8;
                float e = acc[i][j][rr * 2], o = acc[i][j][rr * 2 + 1];
                if (mode == 1) {
                    const int pidx = (n & 63) >> 1;
                    const float cv = g_cos[mm * 32 + pidx];
                    const float sv = g_sin[mm * 32 + pidx];
                    const float e2 = e * cv - o * sv;
                    const float o2 = e * sv + o * cv;
                    e = e2; o = o2;
                }
                if (mode == 3) {
                    *(float2*)(outF + (size_t)mm * D + n) = make_float2(e, o);
                } else {
                    *(uint32_t*)(outH + (size_t)mm * D + n) = pack_h2(e, o);
                }
            }
        }
}

__global__ __launch_bounds__(128, 2) void mm_qkv_kernel() {
    const int z = blockIdx.z;
    const __half* Bh = g_Whi + (size_t)z * D * D;
    if (z == 0)      mm_body(g_Xhi, Bh, 1, (float*)0, g_Qhi);
    else if (z == 1) mm_body(g_Xhi, Bh, 1, (float*)0, g_Khi);
    else             mm_body(g_Xhi, Bh, 2, (float*)0, g_Vhi);
}

__global__ __launch_bounds__(128, 2) void mm_out_kernel(float* __restrict__ out) {
    mm_body(g_Ohi, g_Whi + 3ull * D * D, 3, out, (__half*)0);
}

// ---------------- HMMA flash attention --------------------------------------
// CTA = 64 q rows x 1 head, 4 warps. kv tiles of 64, double-buffered,
// single barrier per kv tile (issue-after-barrier pipeline).
#define AT_SP    144
#define AT_MAT   (64 * AT_SP)
#define AT_KVOFF (1 * AT_MAT)          // after Qh
#define AT_STAGE (2 * AT_MAT)          // Kh, Vh per stage
#define AT_SMEM  (AT_KVOFF + 2 * AT_STAGE)   // 46080 B

__device__ __forceinline__ void at_load64(uint32_t sdst, const __half* g) {
    int t = threadIdx.x;
#pragma unroll
    for (int i = 0; i < 4; i++) {
        int cid = t + i * 128;
        int r = cid >> 3;
        int q = cid & 7;
        cp16(sdst + r * AT_SP + q * 16, g + (size_t)r * D + q * 8);
    }
}

__global__ __launch_bounds__(128, 3) void attn_kernel() {
    extern __shared__ char smem[];
    uint32_t sb = smem_u32(smem);
    const int tid = threadIdx.x, lane = tid & 31, w = tid >> 5;
    const int qt = (int)gridDim.x - 1 - (int)blockIdx.x;   // heavy first
    const int h = blockIdx.y;
    const int qbase = qt * 64;
    const int lr = lane & 15, lc = lane >> 4;
    const int g = lane >> 2, tig = lane & 3;

    // Q + KV tile 0 into stage 0
    at_load64(sb, g_Qhi + (size_t)qbase * D + h * HD);
    at_load64(sb + AT_KVOFF + 0 * AT_MAT, g_Khi + (size_t)h * HD);
    at_load64(sb + AT_KVOFF + 1 * AT_MAT, g_Vhi + (size_t)h * HD);
    asm volatile("cp.async.commit_group;" ::: "memory");

    uint32_t qh[4][4];
    bool qloaded = false;

    float o[8][4];
#pragma unroll
    for (int j = 0; j < 8; j++)
#pragma unroll
        for (int e = 0; e < 4; e++) o[j][e] = 0.0f;
    float m0r = -1e30f, m1r = -1e30f, l0 = 0.0f, l1 = 0.0f;

#pragma unroll 1
    for (int kt = 0; kt <= qt; kt++) {
        asm volatile("cp.async.wait_group 0;" ::: "memory");
        __syncthreads();
        if (kt < qt) {
            const size_t nkoff = (size_t)((kt + 1) * 64) * D + h * HD;
            const uint32_t nb = sb + AT_KVOFF + ((kt + 1) & 1) * AT_STAGE;
            at_load64(nb + 0 * AT_MAT, g_Khi + nkoff);
            at_load64(nb + 1 * AT_MAT, g_Vhi + nkoff);
            asm volatile("cp.async.commit_group;" ::: "memory");
        }

        if (!qloaded) {
            qloaded = true;
#pragma unroll
            for (int ks = 0; ks < 4; ks++)
                ldsm4(sb + (w * 16 + lr) * AT_SP + ks * 32 + lc * 16, qh[ks]);
        }

        const uint32_t kb = sb + AT_KVOFF + (kt & 1) * AT_STAGE;
        const uint32_t sK = kb, sV = kb + AT_MAT;

        float s[8][4];
#pragma unroll
        for (int j = 0; j < 8; j++)
#pragma unroll
            for (int e = 0; e < 4; e++) s[j][e] = 0.0f;

        // --- S = Qh*Kh^T (f32) ---
#pragma unroll
        for (int ks = 0; ks < 4; ks++) {
            uint32_t kh[4][4];
#pragma unroll
            for (int jj = 0; jj < 4; jj++)
                ldsm4(sK + (jj * 16 + lr) * AT_SP + ks * 32 + lc * 16, kh[jj]);
#pragma unroll
            for (int jj = 0; jj < 4; jj++) {
                mma16816(s[2 * jj],     qh[ks], kh[jj][0], kh[jj][2]);
                mma16816(s[2 * jj + 1], qh[ks], kh[jj][1], kh[jj][3]);
            }
        }

        // --- scale into log2 domain + causal mask ---
        const bool diag = (kt == qt);
#pragma unroll
        for (int j = 0; j < 8; j++)
#pragma unroll
            for (int e = 0; e < 4; e++) {
                float v = s[j][e] * SCALE_LOG2E;
                if (diag) {
                    const int kvc = kt * 64 + j * 8 + tig * 2 + (e & 1);
                    const int qr  = qbase + w * 16 + g + ((e >> 1) << 3);
                    if (kvc > qr) v = -1e30f;
                }
                s[j][e] = v;
            }

        // --- online softmax (log2 domain) ---
        float mx0 = -1e30f, mx1 = -1e30f;
#pragma unroll
        for (int j = 0; j < 8; j++) {
            mx0 = fmaxf(mx0, fmaxf(s[j][0], s[j][1]));
            mx1 = fmaxf(mx1, fmaxf(s[j][2], s[j][3]));
        }
        mx0 = fmaxf(mx0, __shfl_xor_sync(0xffffffffu, mx0, 1));
        mx0 = fmaxf(mx0, __shfl_xor_sync(0xffffffffu, mx0, 2));
        mx1 = fmaxf(mx1, __shfl_xor_sync(0xffffffffu, mx1, 1));
        mx1 = fmaxf(mx1, __shfl_xor_sync(0xffffffffu, mx1, 2));
        const float nm0 = fmaxf(m0r, mx0), nm1 = fmaxf(m1r, mx1);
        const float sc0 = ex2(m0r - nm0), sc1 = ex2(m1r - nm1);
        m0r = nm0; m1r = nm1;
        l0 *= sc0; l1 *= sc1;
#pragma unroll
        for (int j = 0; j < 8; j++) {
            o[j][0] *= sc0; o[j][1] *= sc0;
            o[j][2] *= sc1; o[j][3] *= sc1;
        }
#pragma unroll
        for (int j = 0; j < 8; j++) {
            s[j][0] = ex2(s[j][0] - nm0); s[j][1] = ex2(s[j][1] - nm0);
            s[j][2] = ex2(s[j][2] - nm1); s[j][3] = ex2(s[j][3] - nm1);
            l0 += s[j][0] + s[j][1];
            l1 += s[j][2] + s[j][3];
        }

        // --- O += Ph*Vh (f32) ---
#pragma unroll
        for (int ks = 0; ks < 4; ks++) {
            uint32_t pa[4];
#pragma unroll
            for (int hv = 0; hv < 2; hv++) {
                pa[2 * hv]     = pack_h2(s[2 * ks + hv][0], s[2 * ks + hv][1]);
                pa[2 * hv + 1] = pack_h2(s[2 * ks + hv][2], s[2 * ks + hv][3]);
            }
            uint32_t vh[4][4];
#pragma unroll
            for (int jj = 0; jj < 4; jj++)
                ldsm4t(sV + (ks * 16 + lr) * AT_SP + jj * 32 + lc * 16, vh[jj]);
#pragma unroll
            for (int jj = 0; jj < 4; jj++) {
                mma16816(o[2 * jj],     pa, vh[jj][0], vh[jj][1]);
                mma16816(o[2 * jj + 1], pa, vh[jj][2], vh[jj][3]);
            }
        }
    }

    // --- finalize ---
    l0 += __shfl_xor_sync(0xffffffffu, l0, 1);
    l0 += __shfl_xor_sync(0xffffffffu, l0, 2);
    l1 += __shfl_xor_sync(0xffffffffu, l1, 1);
    l1 += __shfl_xor_sync(0xffffffffu, l1, 2);
    const float i0 = 1.0f / l0, i1 = 1.0f / l1;

#pragma unroll
    for (int j = 0; j < 8; j++) {
        const int n = h * HD + j * 8 + tig * 2;
#pragma unroll
        for (int rr = 0; rr < 2; rr++) {
            const int mm = qbase + w * 16 + g + rr * 8;
            const float inv = rr ? i1 : i0;
            *(uint32_t*)(g_Ohi + (size_t)mm * D + n) =
                pack_h2(o[j][2 * rr] * inv, o[j][2 * rr + 1] * inv);
        }
    }
}

// ---------------------------------------------------------------------------
extern "C" void kernel_launch(void* const* d_in, const int* in_sizes, int n_in,
                              void* d_out, int out_size) {
    (void)in_sizes; (void)n_in; (void)out_size;
    const float* x   = (const float*)d_in[0];
    const int*   pos = (const int*)  d_in[1];
    const float* Wq  = (const float*)d_in[2];
    const float* Wk  = (const float*)d_in[3];
    const float* Wv  = (const float*)d_in[4];
    const float* Wo  = (const float*)d_in[5];
    float* out = (float*)d_out;

    cudaFuncSetAttribute(mm_qkv_kernel, cudaFuncAttributeMaxDynamicSharedMemorySize, MM_SMEM);
    cudaFuncSetAttribute(mm_out_kernel, cudaFuncAttributeMaxDynamicSharedMemorySize, MM_SMEM);
    cudaFuncSetAttribute(attn_kernel, cudaFuncAttributeMaxDynamicSharedMemorySize, AT_SMEM);

    prep_kernel<<<(S * D) / 256, 256>>>(x, pos, Wq, Wk, Wv, Wo);

    mm_qkv_kernel<<<dim3(D / 128, S / 128, 3), 128, MM_SMEM>>>();
    attn_kernel<<<dim3(S / 64, H), 128, AT_SMEM>>>();
    mm_out_kernel<<<dim3(D / 128, S / 128, 1), 128, MM_SMEM>>>(out);
}

// round 16
// speedup vs baseline: 1.1578x; 1.0288x over previous
#include <cuda_runtime.h>
#include <cuda_fp16.h>
#include <cstdint>
#include <math.h>

#define S 4096
#define D 1024
#define H 16
#define HD 64
#define SCALE_LOG2E 0.1803368801111204f   // 0.125 * log2(e)

// ---------------- device scratch -------------------------------------------
__device__ __half g_Xhi[(size_t)S * D];
__device__ __half g_Whi[4 * (size_t)D * D];
__device__ __half g_Qhi[(size_t)S * D];
__device__ __half g_Khi[(size_t)S * D];
__device__ __half g_Vhi[(size_t)S * D];
__device__ __half g_Ohi[(size_t)S * D];
__device__ float g_cos[S * 32], g_sin[S * 32];

// ---------------- helpers ---------------------------------------------------
__device__ __forceinline__ uint32_t smem_u32(const void* p) {
    uint32_t a;
    asm("{ .reg .u64 t; cvta.to.shared.u64 t, %1; cvt.u32.u64 %0, t; }"
        : "=r"(a) : "l"(p));
    return a;
}

__device__ __forceinline__ void cp16(uint32_t saddr, const void* g) {
    asm volatile("cp.async.cg.shared.global [%0], [%1], 16;" :: "r"(saddr), "l"(g));
}

__device__ __forceinline__ void ldsm4(uint32_t a, uint32_t r[4]) {
    asm volatile("ldmatrix.sync.aligned.m8n8.x4.shared.b16 {%0,%1,%2,%3}, [%4];"
                 : "=r"(r[0]), "=r"(r[1]), "=r"(r[2]), "=r"(r[3]) : "r"(a));
}

__device__ __forceinline__ void ldsm4t(uint32_t a, uint32_t r[4]) {
    asm volatile("ldmatrix.sync.aligned.m8n8.x4.trans.shared.b16 {%0,%1,%2,%3}, [%4];"
                 : "=r"(r[0]), "=r"(r[1]), "=r"(r[2]), "=r"(r[3]) : "r"(a));
}

__device__ __forceinline__ void mma16816(float c[4], const uint32_t a[4],
                                         uint32_t b0, uint32_t b1) {
    asm("mma.sync.aligned.m16n8k16.row.col.f32.f16.f16.f32 "
        "{%0,%1,%2,%3}, {%4,%5,%6,%7}, {%8,%9}, {%0,%1,%2,%3};"
        : "+f"(c[0]), "+f"(c[1]), "+f"(c[2]), "+f"(c[3])
        : "r"(a[0]), "r"(a[1]), "r"(a[2]), "r"(a[3]), "r"(b0), "r"(b1));
}

__device__ __forceinline__ uint32_t pack_h2(float a, float b) {
    __half2 h = __floats2half2_rn(a, b);
    return *(uint32_t*)&h;
}

__device__ __forceinline__ float ex2(float x) {
    float r;
    asm("ex2.approx.f32 %0, %1;" : "=f"(r) : "f"(x));
    return r;
}

// ---------------- fused, vectorized prep kernel ------------------------------
// 4096 blocks x 256 threads; each thread converts 4 x-elems + 4 W-elems.
__global__ void prep_kernel(const float* __restrict__ x, const int* __restrict__ pos,
                            const float* __restrict__ Wq, const float* __restrict__ Wk,
                            const float* __restrict__ Wv, const float* __restrict__ Wo) {
    size_t base = ((size_t)blockIdx.x * 256 + threadIdx.x) * 4;

    float4 xv = *(const float4*)(x + base);
    uint2 xo;
    xo.x = pack_h2(xv.x, xv.y);
    xo.y = pack_h2(xv.z, xv.w);
    *(uint2*)(g_Xhi + base) = xo;

    const size_t wcap = (size_t)D * D;
    const float* W = (base < wcap) ? Wq : (base < 2 * wcap) ? Wk
                     : (base < 3 * wcap) ? Wv : Wo;
    float4 wv = *(const float4*)(W + (base & (wcap - 1)));
    uint2 wo;
    wo.x = pack_h2(wv.x, wv.y);
    wo.y = pack_h2(wv.z, wv.w);
    *(uint2*)(g_Whi + base) = wo;

    if (threadIdx.x < 32) {   // blockIdx.x in [0, 4096) == S
        int m = blockIdx.x, k = threadIdx.x;
        double f = pow(10000.0, -(double)(2 * k) / 64.0);
        float ang = (float)pos[m] * (float)f;
        float sv, cv;
        sincosf(ang, &sv, &cv);
        g_cos[m * 32 + k] = cv;
        g_sin[m * 32 + k] = sv;
    }
}

// ---------------- fp16 HMMA GEMM (QKV):  Y = A @ B^T --------------------------
// CTA 128x128, 4 warps (2x2), each warp 64x64. k-chunk 64, double-buffered,
// single barrier per k-iteration.
#define MM_SP    144                 // 128B data + 16B pad
#define MM_MAT   (128 * MM_SP)       // 18432 B
#define MM_STAGE (2 * MM_MAT)        // Ah, Bh
#define MM_SMEM  (2 * MM_STAGE)      // 73728 B

__device__ __forceinline__ void mm_load_stage(uint32_t sb, int st, int c,
                                              const __half* A_h, const __half* B_h) {
    const __half* srcs[2] = {A_h, B_h};
    int t = threadIdx.x;
#pragma unroll
    for (int i = 0; i < 16; i++) {
        int cid = t + i * 128;             // 0..2047
        int mi = cid >> 10;
        int r  = (cid >> 3) & 127;
        int q  = cid & 7;
        cp16(sb + st * MM_STAGE + mi * MM_MAT + r * MM_SP + q * 16,
             srcs[mi] + (size_t)r * D + c * 64 + q * 8);
    }
}

__device__ __forceinline__ void mm_stage_compute(uint32_t so, int wm, int wn, int lane,
                                                 float acc[4][8][4]) {
    const int lr = lane & 15, lc = lane >> 4;
#pragma unroll
    for (int ks = 0; ks < 4; ks++) {
        uint32_t a4[4][4], bh[8][2], t4[4];
#pragma unroll
        for (int i = 0; i < 4; i++)
            ldsm4(so + 0 * MM_MAT + (wm * 64 + i * 16 + lr) * MM_SP + ks * 32 + lc * 16, a4[i]);
#pragma unroll
        for (int jj = 0; jj < 4; jj++) {
            ldsm4(so + 1 * MM_MAT + (wn * 64 + jj * 16 + lr) * MM_SP + ks * 32 + lc * 16, t4);
            bh[2 * jj][0] = t4[0]; bh[2 * jj][1] = t4[2];
            bh[2 * jj + 1][0] = t4[1]; bh[2 * jj + 1][1] = t4[3];
        }
#pragma unroll
        for (int i = 0; i < 4; i++)
#pragma unroll
            for (int j = 0; j < 8; j++)
                mma16816(acc[i][j], a4[i], bh[j][0], bh[j][1]);
    }
}

// mode 1: rope + fp16 out (Q/K); 2: fp16 out (V).
__device__ void mm_body(const __half* Ah, const __half* Bh, int mode, __half* outH) {
    extern __shared__ char smem[];
    uint32_t sb = smem_u32(smem);
    const int tid = threadIdx.x, lane = tid & 31, wid = tid >> 5;
    const int wm = wid >> 1, wn = wid & 1;
    const int m0 = blockIdx.y * 128, n0 = blockIdx.x * 128;

    const __half* A_h = Ah + (size_t)m0 * D;
    const __half* B_h = Bh + (size_t)n0 * D;

    float acc[4][8][4];
#pragma unroll
    for (int i = 0; i < 4; i++)
#pragma unroll
        for (int j = 0; j < 8; j++)
#pragma unroll
            for (int e = 0; e < 4; e++) acc[i][j][e] = 0.0f;

    mm_load_stage(sb, 0, 0, A_h, B_h);
    asm volatile("cp.async.commit_group;" ::: "memory");

#pragma unroll 1
    for (int c = 0; c < 16; c++) {
        int st = c & 1;
        asm volatile("cp.async.wait_group 0;" ::: "memory");
        __syncthreads();
        if (c + 1 < 16) {
            mm_load_stage(sb, st ^ 1, c + 1, A_h, B_h);
            asm volatile("cp.async.commit_group;" ::: "memory");
        }
        mm_stage_compute(sb + st * MM_STAGE, wm, wn, lane, acc);
    }

    const int g = lane >> 2, tig = lane & 3;
#pragma unroll
    for (int i = 0; i < 4; i++)
#pragma unroll
        for (int j = 0; j < 8; j++) {
            const int m = m0 + wm * 64 + i * 16 + g;
            const int n = n0 + wn * 64 + j * 8 + tig * 2;
#pragma unroll
            for (int rr = 0; rr < 2; rr++) {
                const int mm = m + rr * 8;
                float e = acc[i][j][rr * 2], o = acc[i][j][rr * 2 + 1];
                if (mode == 1) {
                    const int pidx = (n & 63) >> 1;
                    const float cv = g_cos[mm * 32 + pidx];
                    const float sv = g_sin[mm * 32 + pidx];
                    const float e2 = e * cv - o * sv;
                    const float o2 = e * sv + o * cv;
                    e = e2; o = o2;
                }
                *(uint32_t*)(outH + (size_t)mm * D + n) = pack_h2(e, o);
            }
        }
}

__global__ __launch_bounds__(128, 2) void mm_qkv_kernel() {
    const int z = blockIdx.z;
    const __half* Bh = g_Whi + (size_t)z * D * D;
    if (z == 0)      mm_body(g_Xhi, Bh, 1, g_Qhi);
    else if (z == 1) mm_body(g_Xhi, Bh, 1, g_Khi);
    else             mm_body(g_Xhi, Bh, 2, g_Vhi);
}

// ---------------- mm_out: 64x128 CTA tiles, 4 CTAs/SM, single wave -----------
#define MO_AMAT  (64 * MM_SP)          // 9216 B
#define MO_BMAT  (128 * MM_SP)         // 18432 B
#define MO_STAGE (MO_AMAT + MO_BMAT)   // 27648 B
#define MO_SMEM  (2 * MO_STAGE)        // 55296 B

__device__ __forceinline__ void mo_load_stage(uint32_t sb, int st, int c,
                                              const __half* A_h, const __half* B_h) {
    int t = threadIdx.x;
#pragma unroll
    for (int i = 0; i < 12; i++) {
        int cid = t + i * 128;             // 0..1535
        if (cid < 512) {                   // A: 64 rows
            int r = cid >> 3, q = cid & 7;
            cp16(sb + st * MO_STAGE + r * MM_SP + q * 16,
                 A_h + (size_t)r * D + c * 64 + q * 8);
        } else {                           // B: 128 rows
            int c2 = cid - 512;
            int r = c2 >> 3, q = c2 & 7;
            cp16(sb + st * MO_STAGE + MO_AMAT + r * MM_SP + q * 16,
                 B_h + (size_t)r * D + c * 64 + q * 8);
        }
    }
}

__global__ __launch_bounds__(128, 4) void mm_out_kernel(float* __restrict__ out) {
    extern __shared__ char smem[];
    uint32_t sb = smem_u32(smem);
    const int tid = threadIdx.x, lane = tid & 31, wid = tid >> 5;
    const int wm = wid & 1, wn = wid >> 1;          // 2x2 grid of 32x64 warp tiles
    const int m0 = blockIdx.y * 64, n0 = blockIdx.x * 128;
    const int lr = lane & 15, lc = lane >> 4;

    const __half* A_h = g_Ohi + (size_t)m0 * D;
    const __half* B_h = g_Whi + 3ull * D * D + (size_t)n0 * D;

    float acc[2][8][4];
#pragma unroll
    for (int i = 0; i < 2; i++)
#pragma unroll
        for (int j = 0; j < 8; j++)
#pragma unroll
            for (int e = 0; e < 4; e++) acc[i][j][e] = 0.0f;

    mo_load_stage(sb, 0, 0, A_h, B_h);
    asm volatile("cp.async.commit_group;" ::: "memory");

#pragma unroll 1
    for (int c = 0; c < 16; c++) {
        int st = c & 1;
        asm volatile("cp.async.wait_group 0;" ::: "memory");
        __syncthreads();
        if (c + 1 < 16) {
            mo_load_stage(sb, st ^ 1, c + 1, A_h, B_h);
            asm volatile("cp.async.commit_group;" ::: "memory");
        }
        const uint32_t so = sb + st * MO_STAGE;
#pragma unroll
        for (int ks = 0; ks < 4; ks++) {
            uint32_t a4[2][4], bh[8][2], t4[4];
#pragma unroll
            for (int i = 0; i < 2; i++)
                ldsm4(so + (wm * 32 + i * 16 + lr) * MM_SP + ks * 32 + lc * 16, a4[i]);
#pragma unroll
            for (int jj = 0; jj < 4; jj++) {
                ldsm4(so + MO_AMAT + (wn * 64 + jj * 16 + lr) * MM_SP + ks * 32 + lc * 16, t4);
                bh[2 * jj][0] = t4[0]; bh[2 * jj][1] = t4[2];
                bh[2 * jj + 1][0] = t4[1]; bh[2 * jj + 1][1] = t4[3];
            }
#pragma unroll
            for (int i = 0; i < 2; i++)
#pragma unroll
                for (int j = 0; j < 8; j++)
                    mma16816(acc[i][j], a4[i], bh[j][0], bh[j][1]);
        }
    }

    const int g = lane >> 2, tig = lane & 3;
#pragma unroll
    for (int i = 0; i < 2; i++)
#pragma unroll
        for (int j = 0; j < 8; j++) {
            const int m = m0 + wm * 32 + i * 16 + g;
            const int n = n0 + wn * 64 + j * 8 + tig * 2;
#pragma unroll
            for (int rr = 0; rr < 2; rr++) {
                const int mm = m + rr * 8;
                *(float2*)(out + (size_t)mm * D + n) =
                    make_float2(acc[i][j][rr * 2], acc[i][j][rr * 2 + 1]);
            }
        }
}

// ---------------- HMMA flash attention --------------------------------------
// CTA = 64 q rows x 1 head, 4 warps. kv tiles of 64, double-buffered,
// single barrier per kv tile. ex2-domain softmax.
#define AT_SP    144
#define AT_MAT   (64 * AT_SP)
#define AT_KVOFF (1 * AT_MAT)
#define AT_STAGE (2 * AT_MAT)
#define AT_SMEM  (AT_KVOFF + 2 * AT_STAGE)   // 46080 B

__device__ __forceinline__ void at_load64(uint32_t sdst, const __half* g) {
    int t = threadIdx.x;
#pragma unroll
    for (int i = 0; i < 4; i++) {
        int cid = t + i * 128;
        int r = cid >> 3;
        int q = cid & 7;
        cp16(sdst + r * AT_SP + q * 16, g + (size_t)r * D + q * 8);
    }
}

__global__ __launch_bounds__(128, 3) void attn_kernel() {
    extern __shared__ char smem[];
    uint32_t sb = smem_u32(smem);
    const int tid = threadIdx.x, lane = tid & 31, w = tid >> 5;
    const int qt = (int)gridDim.x - 1 - (int)blockIdx.x;   // heavy first
    const int h = blockIdx.y;
    const int qbase = qt * 64;
    const int lr = lane & 15, lc = lane >> 4;
    const int g = lane >> 2, tig = lane & 3;

    at_load64(sb, g_Qhi + (size_t)qbase * D + h * HD);
    at_load64(sb + AT_KVOFF + 0 * AT_MAT, g_Khi + (size_t)h * HD);
    at_load64(sb + AT_KVOFF + 1 * AT_MAT, g_Vhi + (size_t)h * HD);
    asm volatile("cp.async.commit_group;" ::: "memory");

    uint32_t qh[4][4];
    bool qloaded = false;

    float o[8][4];
#pragma unroll
    for (int j = 0; j < 8; j++)
#pragma unroll
        for (int e = 0; e < 4; e++) o[j][e] = 0.0f;
    float m0r = -1e30f, m1r = -1e30f, l0 = 0.0f, l1 = 0.0f;

#pragma unroll 1
    for (int kt = 0; kt <= qt; kt++) {
        asm volatile("cp.async.wait_group 0;" ::: "memory");
        __syncthreads();
        if (kt < qt) {
            const size_t nkoff = (size_t)((kt + 1) * 64) * D + h * HD;
            const uint32_t nb = sb + AT_KVOFF + ((kt + 1) & 1) * AT_STAGE;
            at_load64(nb + 0 * AT_MAT, g_Khi + nkoff);
            at_load64(nb + 1 * AT_MAT, g_Vhi + nkoff);
            asm volatile("cp.async.commit_group;" ::: "memory");
        }

        if (!qloaded) {
            qloaded = true;
#pragma unroll
            for (int ks = 0; ks < 4; ks++)
                ldsm4(sb + (w * 16 + lr) * AT_SP + ks * 32 + lc * 16, qh[ks]);
        }

        const uint32_t kb = sb + AT_KVOFF + (kt & 1) * AT_STAGE;
        const uint32_t sK = kb, sV = kb + AT_MAT;

        float s[8][4];
#pragma unroll
        for (int j = 0; j < 8; j++)
#pragma unroll
            for (int e = 0; e < 4; e++) s[j][e] = 0.0f;

#pragma unroll
        for (int ks = 0; ks < 4; ks++) {
            uint32_t kh[4][4];
#pragma unroll
            for (int jj = 0; jj < 4; jj++)
                ldsm4(sK + (jj * 16 + lr) * AT_SP + ks * 32 + lc * 16, kh[jj]);
#pragma unroll
            for (int jj = 0; jj < 4; jj++) {
                mma16816(s[2 * jj],     qh[ks], kh[jj][0], kh[jj][2]);
                mma16816(s[2 * jj + 1], qh[ks], kh[jj][1], kh[jj][3]);
            }
        }

        const bool diag = (kt == qt);
#pragma unroll
        for (int j = 0; j < 8; j++)
#pragma unroll
            for (int e = 0; e < 4; e++) {
                float v = s[j][e] * SCALE_LOG2E;
                if (diag) {
                    const int kvc = kt * 64 + j * 8 + tig * 2 + (e & 1);
                    const int qr  = qbase + w * 16 + g + ((e >> 1) << 3);
                    if (kvc > qr) v = -1e30f;
                }
                s[j][e] = v;
            }

        float mx0 = -1e30f, mx1 = -1e30f;
#pragma unroll
        for (int j = 0; j < 8; j++) {
            mx0 = fmaxf(mx0, fmaxf(s[j][0], s[j][1]));
            mx1 = fmaxf(mx1, fmaxf(s[j][2], s[j][3]));
        }
        mx0 = fmaxf(mx0, __shfl_xor_sync(0xffffffffu, mx0, 1));
        mx0 = fmaxf(mx0, __shfl_xor_sync(0xffffffffu, mx0, 2));
        mx1 = fmaxf(mx1, __shfl_xor_sync(0xffffffffu, mx1, 1));
        mx1 = fmaxf(mx1, __shfl_xor_sync(0xffffffffu, mx1, 2));
        const float nm0 = fmaxf(m0r, mx0), nm1 = fmaxf(m1r, mx1);
        const float sc0 = ex2(m0r - nm0), sc1 = ex2(m1r - nm1);
        m0r = nm0; m1r = nm1;
        l0 *= sc0; l1 *= sc1;
#pragma unroll
        for (int j = 0; j < 8; j++) {
            o[j][0] *= sc0; o[j][1] *= sc0;
            o[j][2] *= sc1; o[j][3] *= sc1;
        }
#pragma unroll
        for (int j = 0; j < 8; j++) {
            s[j][0] = ex2(s[j][0] - nm0); s[j][1] = ex2(s[j][1] - nm0);
            s[j][2] = ex2(s[j][2] - nm1); s[j][3] = ex2(s[j][3] - nm1);
            l0 += s[j][0] + s[j][1];
            l1 += s[j][2] + s[j][3];
        }

#pragma unroll
        for (int ks = 0; ks < 4; ks++) {
            uint32_t pa[4];
#pragma unroll
            for (int hv = 0; hv < 2; hv++) {
                pa[2 * hv]     = pack_h2(s[2 * ks + hv][0], s[2 * ks + hv][1]);
                pa[2 * hv + 1] = pack_h2(s[2 * ks + hv][2], s[2 * ks + hv][3]);
            }
            uint32_t vh[4][4];
#pragma unroll
            for (int jj = 0; jj < 4; jj++)
                ldsm4t(sV + (ks * 16 + lr) * AT_SP + jj * 32 + lc * 16, vh[jj]);
#pragma unroll
            for (int jj = 0; jj < 4; jj++) {
                mma16816(o[2 * jj],     pa, vh[jj][0], vh[jj][1]);
                mma16816(o[2 * jj + 1], pa, vh[jj][2], vh[jj][3]);
            }
        }
    }

    l0 += __shfl_xor_sync(0xffffffffu, l0, 1);
    l0 += __shfl_xor_sync(0xffffffffu, l0, 2);
    l1 += __shfl_xor_sync(0xffffffffu, l1, 1);
    l1 += __shfl_xor_sync(0xffffffffu, l1, 2);
    const float i0 = 1.0f / l0, i1 = 1.0f / l1;

#pragma unroll
    for (int j = 0; j < 8; j++) {
        const int n = h * HD + j * 8 + tig * 2;
#pragma unroll
        for (int rr = 0; rr < 2; rr++) {
            const int mm = qbase + w * 16 + g + rr * 8;
            const float inv = rr ? i1 : i0;
            *(uint32_t*)(g_Ohi + (size_t)mm * D + n) =
                pack_h2(o[j][2 * rr] * inv, o[j][2 * rr + 1] * inv);
        }
    }
}

// ---------------------------------------------------------------------------
extern "C" void kernel_launch(void* const* d_in, const int* in_sizes, int n_in,
                              void* d_out, int out_size) {
    (void)in_sizes; (void)n_in; (void)out_size;
    const float* x   = (const float*)d_in[0];
    const int*   pos = (const int*)  d_in[1];
    const float* Wq  = (const float*)d_in[2];
    const float* Wk  = (const float*)d_in[3];
    const float* Wv  = (const float*)d_in[4];
    const float* Wo  = (const float*)d_in[5];
    float* out = (float*)d_out;

    cudaFuncSetAttribute(mm_qkv_kernel, cudaFuncAttributeMaxDynamicSharedMemorySize, MM_SMEM);
    cudaFuncSetAttribute(mm_out_kernel, cudaFuncAttributeMaxDynamicSharedMemorySize, MO_SMEM);
    cudaFuncSetAttribute(attn_kernel, cudaFuncAttributeMaxDynamicSharedMemorySize, AT_SMEM);

    prep_kernel<<<(S * D) / 1024, 256>>>(x, pos, Wq, Wk, Wv, Wo);

    mm_qkv_kernel<<<dim3(D / 128, S / 128, 3), 128, MM_SMEM>>>();
    attn_kernel<<<dim3(S / 64, H), 128, AT_SMEM>>>();
    mm_out_kernel<<<dim3(D / 128, S / 64), 128, MO_SMEM>>>(out);
}

// round 17
// speedup vs baseline: 1.1853x; 1.0238x over previous
#include <cuda_runtime.h>
#include <cuda_fp16.h>
#include <cstdint>
#include <math.h>

#define S 4096
#define D 1024
#define H 16
#define HD 64
#define SCALE_LOG2E 0.1803368801111204f   // 0.125 * log2(e)

// ---------------- device scratch -------------------------------------------
__device__ __half g_Xhi[(size_t)S * D];
__device__ __half g_Whi[4 * (size_t)D * D];
__device__ __half g_Qhi[(size_t)S * D];
__device__ __half g_Khi[(size_t)S * D];
__device__ __half g_Vhi[(size_t)S * D];
__device__ __half g_Ohi[(size_t)S * D];
__device__ float g_cos[S * 32], g_sin[S * 32];

// ---------------- helpers ---------------------------------------------------
__device__ __forceinline__ uint32_t smem_u32(const void* p) {
    uint32_t a;
    asm("{ .reg .u64 t; cvta.to.shared.u64 t, %1; cvt.u32.u64 %0, t; }"
        : "=r"(a) : "l"(p));
    return a;
}

__device__ __forceinline__ void cp16(uint32_t saddr, const void* g) {
    asm volatile("cp.async.cg.shared.global [%0], [%1], 16;" :: "r"(saddr), "l"(g));
}

__device__ __forceinline__ void ldsm4(uint32_t a, uint32_t r[4]) {
    asm volatile("ldmatrix.sync.aligned.m8n8.x4.shared.b16 {%0,%1,%2,%3}, [%4];"
                 : "=r"(r[0]), "=r"(r[1]), "=r"(r[2]), "=r"(r[3]) : "r"(a));
}

__device__ __forceinline__ void ldsm4t(uint32_t a, uint32_t r[4]) {
    asm volatile("ldmatrix.sync.aligned.m8n8.x4.trans.shared.b16 {%0,%1,%2,%3}, [%4];"
                 : "=r"(r[0]), "=r"(r[1]), "=r"(r[2]), "=r"(r[3]) : "r"(a));
}

__device__ __forceinline__ void mma16816(float c[4], const uint32_t a[4],
                                         uint32_t b0, uint32_t b1) {
    asm("mma.sync.aligned.m16n8k16.row.col.f32.f16.f16.f32 "
        "{%0,%1,%2,%3}, {%4,%5,%6,%7}, {%8,%9}, {%0,%1,%2,%3};"
        : "+f"(c[0]), "+f"(c[1]), "+f"(c[2]), "+f"(c[3])
        : "r"(a[0]), "r"(a[1]), "r"(a[2]), "r"(a[3]), "r"(b0), "r"(b1));
}

__device__ __forceinline__ uint32_t pack_h2(float a, float b) {
    __half2 h = __floats2half2_rn(a, b);
    return *(uint32_t*)&h;
}

__device__ __forceinline__ float ex2(float x) {
    float r;
    asm("ex2.approx.f32 %0, %1;" : "=f"(r) : "f"(x));
    return r;
}

// ---------------- fused, vectorized prep kernel ------------------------------
__global__ void prep_kernel(const float* __restrict__ x, const int* __restrict__ pos,
                            const float* __restrict__ Wq, const float* __restrict__ Wk,
                            const float* __restrict__ Wv, const float* __restrict__ Wo) {
    size_t base = ((size_t)blockIdx.x * 256 + threadIdx.x) * 4;

    float4 xv = *(const float4*)(x + base);
    uint2 xo;
    xo.x = pack_h2(xv.x, xv.y);
    xo.y = pack_h2(xv.z, xv.w);
    *(uint2*)(g_Xhi + base) = xo;

    const size_t wcap = (size_t)D * D;
    const float* W = (base < wcap) ? Wq : (base < 2 * wcap) ? Wk
                     : (base < 3 * wcap) ? Wv : Wo;
    float4 wv = *(const float4*)(W + (base & (wcap - 1)));
    uint2 wo;
    wo.x = pack_h2(wv.x, wv.y);
    wo.y = pack_h2(wv.z, wv.w);
    *(uint2*)(g_Whi + base) = wo;

    if (threadIdx.x < 32) {   // blockIdx.x in [0, 4096) == S
        int m = blockIdx.x, k = threadIdx.x;
        double f = pow(10000.0, -(double)(2 * k) / 64.0);
        float ang = (float)pos[m] * (float)f;
        float sv, cv;
        sincosf(ang, &sv, &cv);
        g_cos[m * 32 + k] = cv;
        g_sin[m * 32 + k] = sv;
    }
}

// ---------------- fp16 HMMA GEMM (QKV):  Y = A @ B^T --------------------------
#define MM_SP    144                 // 128B data + 16B pad
#define MM_MAT   (128 * MM_SP)       // 18432 B
#define MM_STAGE (2 * MM_MAT)        // Ah, Bh
#define MM_SMEM  (2 * MM_STAGE)      // 73728 B

__device__ __forceinline__ void mm_load_stage(uint32_t sb, int st, int c,
                                              const __half* A_h, const __half* B_h) {
    const __half* srcs[2] = {A_h, B_h};
    int t = threadIdx.x;
#pragma unroll
    for (int i = 0; i < 16; i++) {
        int cid = t + i * 128;             // 0..2047
        int mi = cid >> 10;
        int r  = (cid >> 3) & 127;
        int q  = cid & 7;
        cp16(sb + st * MM_STAGE + mi * MM_MAT + r * MM_SP + q * 16,
             srcs[mi] + (size_t)r * D + c * 64 + q * 8);
    }
}

__device__ __forceinline__ void mm_stage_compute(uint32_t so, int wm, int wn, int lane,
                                                 float acc[4][8][4]) {
    const int lr = lane & 15, lc = lane >> 4;
#pragma unroll
    for (int ks = 0; ks < 4; ks++) {
        uint32_t a4[4][4], bh[8][2], t4[4];
#pragma unroll
        for (int i = 0; i < 4; i++)
            ldsm4(so + 0 * MM_MAT + (wm * 64 + i * 16 + lr) * MM_SP + ks * 32 + lc * 16, a4[i]);
#pragma unroll
        for (int jj = 0; jj < 4; jj++) {
            ldsm4(so + 1 * MM_MAT + (wn * 64 + jj * 16 + lr) * MM_SP + ks * 32 + lc * 16, t4);
            bh[2 * jj][0] = t4[0]; bh[2 * jj][1] = t4[2];
            bh[2 * jj + 1][0] = t4[1]; bh[2 * jj + 1][1] = t4[3];
        }
#pragma unroll
        for (int i = 0; i < 4; i++)
#pragma unroll
            for (int j = 0; j < 8; j++)
                mma16816(acc[i][j], a4[i], bh[j][0], bh[j][1]);
    }
}

// mode 1: rope + fp16 out (Q/K); 2: fp16 out (V).
__device__ void mm_body(const __half* Ah, const __half* Bh, int mode, __half* outH) {
    extern __shared__ char smem[];
    uint32_t sb = smem_u32(smem);
    const int tid = threadIdx.x, lane = tid & 31, wid = tid >> 5;
    const int wm = wid >> 1, wn = wid & 1;
    const int m0 = blockIdx.y * 128, n0 = blockIdx.x * 128;

    const __half* A_h = Ah + (size_t)m0 * D;
    const __half* B_h = Bh + (size_t)n0 * D;

    float acc[4][8][4];
#pragma unroll
    for (int i = 0; i < 4; i++)
#pragma unroll
        for (int j = 0; j < 8; j++)
#pragma unroll
            for (int e = 0; e < 4; e++) acc[i][j][e] = 0.0f;

    mm_load_stage(sb, 0, 0, A_h, B_h);
    asm volatile("cp.async.commit_group;" ::: "memory");

#pragma unroll 1
    for (int c = 0; c < 16; c++) {
        int st = c & 1;
        asm volatile("cp.async.wait_group 0;" ::: "memory");
        __syncthreads();
        if (c + 1 < 16) {
            mm_load_stage(sb, st ^ 1, c + 1, A_h, B_h);
            asm volatile("cp.async.commit_group;" ::: "memory");
        }
        mm_stage_compute(sb + st * MM_STAGE, wm, wn, lane, acc);
    }

    const int g = lane >> 2, tig = lane & 3;
#pragma unroll
    for (int i = 0; i < 4; i++)
#pragma unroll
        for (int j = 0; j < 8; j++) {
            const int m = m0 + wm * 64 + i * 16 + g;
            const int n = n0 + wn * 64 + j * 8 + tig * 2;
#pragma unroll
            for (int rr = 0; rr < 2; rr++) {
                const int mm = m + rr * 8;
                float e = acc[i][j][rr * 2], o = acc[i][j][rr * 2 + 1];
                if (mode == 1) {
                    const int pidx = (n & 63) >> 1;
                    const float cv = g_cos[mm * 32 + pidx];
                    const float sv = g_sin[mm * 32 + pidx];
                    const float e2 = e * cv - o * sv;
                    const float o2 = e * sv + o * cv;
                    e = e2; o = o2;
                }
                *(uint32_t*)(outH + (size_t)mm * D + n) = pack_h2(e, o);
            }
        }
}

__global__ __launch_bounds__(128, 2) void mm_qkv_kernel() {
    const int z = blockIdx.z;
    const __half* Bh = g_Whi + (size_t)z * D * D;
    if (z == 0)      mm_body(g_Xhi, Bh, 1, g_Qhi);
    else if (z == 1) mm_body(g_Xhi, Bh, 1, g_Khi);
    else             mm_body(g_Xhi, Bh, 2, g_Vhi);
}

// ---------------- mm_out: 64x128 CTA tiles, 4 CTAs/SM, single wave -----------
#define MO_AMAT  (64 * MM_SP)          // 9216 B
#define MO_BMAT  (128 * MM_SP)         // 18432 B
#define MO_STAGE (MO_AMAT + MO_BMAT)   // 27648 B
#define MO_SMEM  (2 * MO_STAGE)        // 55296 B

__device__ __forceinline__ void mo_load_stage(uint32_t sb, int st, int c,
                                              const __half* A_h, const __half* B_h) {
    int t = threadIdx.x;
#pragma unroll
    for (int i = 0; i < 12; i++) {
        int cid = t + i * 128;             // 0..1535
        if (cid < 512) {
            int r = cid >> 3, q = cid & 7;
            cp16(sb + st * MO_STAGE + r * MM_SP + q * 16,
                 A_h + (size_t)r * D + c * 64 + q * 8);
        } else {
            int c2 = cid - 512;
            int r = c2 >> 3, q = c2 & 7;
            cp16(sb + st * MO_STAGE + MO_AMAT + r * MM_SP + q * 16,
                 B_h + (size_t)r * D + c * 64 + q * 8);
        }
    }
}

__global__ __launch_bounds__(128, 4) void mm_out_kernel(float* __restrict__ out) {
    extern __shared__ char smem[];
    uint32_t sb = smem_u32(smem);
    const int tid = threadIdx.x, lane = tid & 31, wid = tid >> 5;
    const int wm = wid & 1, wn = wid >> 1;
    const int m0 = blockIdx.y * 64, n0 = blockIdx.x * 128;
    const int lr = lane & 15, lc = lane >> 4;

    const __half* A_h = g_Ohi + (size_t)m0 * D;
    const __half* B_h = g_Whi + 3ull * D * D + (size_t)n0 * D;

    float acc[2][8][4];
#pragma unroll
    for (int i = 0; i < 2; i++)
#pragma unroll
        for (int j = 0; j < 8; j++)
#pragma unroll
            for (int e = 0; e < 4; e++) acc[i][j][e] = 0.0f;

    mo_load_stage(sb, 0, 0, A_h, B_h);
    asm volatile("cp.async.commit_group;" ::: "memory");

#pragma unroll 1
    for (int c = 0; c < 16; c++) {
        int st = c & 1;
        asm volatile("cp.async.wait_group 0;" ::: "memory");
        __syncthreads();
        if (c + 1 < 16) {
            mo_load_stage(sb, st ^ 1, c + 1, A_h, B_h);
            asm volatile("cp.async.commit_group;" ::: "memory");
        }
        const uint32_t so = sb + st * MO_STAGE;
#pragma unroll
        for (int ks = 0; ks < 4; ks++) {
            uint32_t a4[2][4], bh[8][2], t4[4];
#pragma unroll
            for (int i = 0; i < 2; i++)
                ldsm4(so + (wm * 32 + i * 16 + lr) * MM_SP + ks * 32 + lc * 16, a4[i]);
#pragma unroll
            for (int jj = 0; jj < 4; jj++) {
                ldsm4(so + MO_AMAT + (wn * 64 + jj * 16 + lr) * MM_SP + ks * 32 + lc * 16, t4);
                bh[2 * jj][0] = t4[0]; bh[2 * jj][1] = t4[2];
                bh[2 * jj + 1][0] = t4[1]; bh[2 * jj + 1][1] = t4[3];
            }
#pragma unroll
            for (int i = 0; i < 2; i++)
#pragma unroll
                for (int j = 0; j < 8; j++)
                    mma16816(acc[i][j], a4[i], bh[j][0], bh[j][1]);
        }
    }

    const int g = lane >> 2, tig = lane & 3;
#pragma unroll
    for (int i = 0; i < 2; i++)
#pragma unroll
        for (int j = 0; j < 8; j++) {
            const int m = m0 + wm * 32 + i * 16 + g;
            const int n = n0 + wn * 64 + j * 8 + tig * 2;
#pragma unroll
            for (int rr = 0; rr < 2; rr++) {
                const int mm = m + rr * 8;
                *(float2*)(out + (size_t)mm * D + n) =
                    make_float2(acc[i][j][rr * 2], acc[i][j][rr * 2 + 1]);
            }
        }
}

// ---------------- HMMA flash attention --------------------------------------
// CTA = 64 q rows x 1 head, 4 warps, 4 CTAs/SM. Q fragments re-loaded from
// smem each tile (frees 16 persistent regs -> fits 128-reg budget).
#define AT_SP    144
#define AT_MAT   (64 * AT_SP)
#define AT_KVOFF (1 * AT_MAT)
#define AT_STAGE (2 * AT_MAT)
#define AT_SMEM  (AT_KVOFF + 2 * AT_STAGE)   // 46080 B

__device__ __forceinline__ void at_load64(uint32_t sdst, const __half* g) {
    int t = threadIdx.x;
#pragma unroll
    for (int i = 0; i < 4; i++) {
        int cid = t + i * 128;
        int r = cid >> 3;
        int q = cid & 7;
        cp16(sdst + r * AT_SP + q * 16, g + (size_t)r * D + q * 8);
    }
}

__global__ __launch_bounds__(128, 4) void attn_kernel() {
    extern __shared__ char smem[];
    uint32_t sb = smem_u32(smem);
    const int tid = threadIdx.x, lane = tid & 31, w = tid >> 5;
    const int qt = (int)gridDim.x - 1 - (int)blockIdx.x;   // heavy first
    const int h = blockIdx.y;
    const int qbase = qt * 64;
    const int lr = lane & 15, lc = lane >> 4;
    const int g = lane >> 2, tig = lane & 3;

    at_load64(sb, g_Qhi + (size_t)qbase * D + h * HD);
    at_load64(sb + AT_KVOFF + 0 * AT_MAT, g_Khi + (size_t)h * HD);
    at_load64(sb + AT_KVOFF + 1 * AT_MAT, g_Vhi + (size_t)h * HD);
    asm volatile("cp.async.commit_group;" ::: "memory");

    float o[8][4];
#pragma unroll
    for (int j = 0; j < 8; j++)
#pragma unroll
        for (int e = 0; e < 4; e++) o[j][e] = 0.0f;
    float m0r = -1e30f, m1r = -1e30f, l0 = 0.0f, l1 = 0.0f;

#pragma unroll 1
    for (int kt = 0; kt <= qt; kt++) {
        asm volatile("cp.async.wait_group 0;" ::: "memory");
        __syncthreads();
        if (kt < qt) {
            const size_t nkoff = (size_t)((kt + 1) * 64) * D + h * HD;
            const uint32_t nb = sb + AT_KVOFF + ((kt + 1) & 1) * AT_STAGE;
            at_load64(nb + 0 * AT_MAT, g_Khi + nkoff);
            at_load64(nb + 1 * AT_MAT, g_Vhi + nkoff);
            asm volatile("cp.async.commit_group;" ::: "memory");
        }

        const uint32_t kb = sb + AT_KVOFF + (kt & 1) * AT_STAGE;
        const uint32_t sK = kb, sV = kb + AT_MAT;

        float s[8][4];
#pragma unroll
        for (int j = 0; j < 8; j++)
#pragma unroll
            for (int e = 0; e < 4; e++) s[j][e] = 0.0f;

        // --- S = Q*K^T (f32); Q fragments re-loaded from resident smem ---
#pragma unroll
        for (int ks = 0; ks < 4; ks++) {
            uint32_t qf[4], kh[4][4];
            ldsm4(sb + (w * 16 + lr) * AT_SP + ks * 32 + lc * 16, qf);
#pragma unroll
            for (int jj = 0; jj < 4; jj++)
                ldsm4(sK + (jj * 16 + lr) * AT_SP + ks * 32 + lc * 16, kh[jj]);
#pragma unroll
            for (int jj = 0; jj < 4; jj++) {
                mma16816(s[2 * jj],     qf, kh[jj][0], kh[jj][2]);
                mma16816(s[2 * jj + 1], qf, kh[jj][1], kh[jj][3]);
            }
        }

        const bool diag = (kt == qt);
#pragma unroll
        for (int j = 0; j < 8; j++)
#pragma unroll
            for (int e = 0; e < 4; e++) {
                float v = s[j][e] * SCALE_LOG2E;
                if (diag) {
                    const int kvc = kt * 64 + j * 8 + tig * 2 + (e & 1);
                    const int qr  = qbase + w * 16 + g + ((e >> 1) << 3);
                    if (kvc > qr) v = -1e30f;
                }
                s[j][e] = v;
            }

        float mx0 = -1e30f, mx1 = -1e30f;
#pragma unroll
        for (int j = 0; j < 8; j++) {
            mx0 = fmaxf(mx0, fmaxf(s[j][0], s[j][1]));
            mx1 = fmaxf(mx1, fmaxf(s[j][2], s[j][3]));
        }
        mx0 = fmaxf(mx0, __shfl_xor_sync(0xffffffffu, mx0, 1));
        mx0 = fmaxf(mx0, __shfl_xor_sync(0xffffffffu, mx0, 2));
        mx1 = fmaxf(mx1, __shfl_xor_sync(0xffffffffu, mx1, 1));
        mx1 = fmaxf(mx1, __shfl_xor_sync(0xffffffffu, mx1, 2));
        const float nm0 = fmaxf(m0r, mx0), nm1 = fmaxf(m1r, mx1);
        const float sc0 = ex2(m0r - nm0), sc1 = ex2(m1r - nm1);
        m0r = nm0; m1r = nm1;
        l0 *= sc0; l1 *= sc1;
#pragma unroll
        for (int j = 0; j < 8; j++) {
            o[j][0] *= sc0; o[j][1] *= sc0;
            o[j][2] *= sc1; o[j][3] *= sc1;
        }
#pragma unroll
        for (int j = 0; j < 8; j++) {
            s[j][0] = ex2(s[j][0] - nm0); s[j][1] = ex2(s[j][1] - nm0);
            s[j][2] = ex2(s[j][2] - nm1); s[j][3] = ex2(s[j][3] - nm1);
            l0 += s[j][0] + s[j][1];
            l1 += s[j][2] + s[j][3];
        }

#pragma unroll
        for (int ks = 0; ks < 4; ks++) {
            uint32_t pa[4];
#pragma unroll
            for (int hv = 0; hv < 2; hv++) {
                pa[2 * hv]     = pack_h2(s[2 * ks + hv][0], s[2 * ks + hv][1]);
                pa[2 * hv + 1] = pack_h2(s[2 * ks + hv][2], s[2 * ks + hv][3]);
            }
            uint32_t vh[4][4];
#pragma unroll
            for (int jj = 0; jj < 4; jj++)
                ldsm4t(sV + (ks * 16 + lr) * AT_SP + jj * 32 + lc * 16, vh[jj]);
#pragma unroll
            for (int jj = 0; jj < 4; jj++) {
                mma16816(o[2 * jj],     pa, vh[jj][0], vh[jj][1]);
                mma16816(o[2 * jj + 1], pa, vh[jj][2], vh[jj][3]);
            }
        }
    }

    l0 += __shfl_xor_sync(0xffffffffu, l0, 1);
    l0 += __shfl_xor_sync(0xffffffffu, l0, 2);
    l1 += __shfl_xor_sync(0xffffffffu, l1, 1);
    l1 += __shfl_xor_sync(0xffffffffu, l1, 2);
    const float i0 = 1.0f / l0, i1 = 1.0f / l1;

#pragma unroll
    for (int j = 0; j < 8; j++) {
        const int n = h * HD + j * 8 + tig * 2;
#pragma unroll
        for (int rr = 0; rr < 2; rr++) {
            const int mm = qbase + w * 16 + g + rr * 8;
            const float inv = rr ? i1 : i0;
            *(uint32_t*)(g_Ohi + (size_t)mm * D + n) =
                pack_h2(o[j][2 * rr] * inv, o[j][2 * rr + 1] * inv);
        }
    }
}

// ---------------------------------------------------------------------------
extern "C" void kernel_launch(void* const* d_in, const int* in_sizes, int n_in,
                              void* d_out, int out_size) {
    (void)in_sizes; (void)n_in; (void)out_size;
    const float* x   = (const float*)d_in[0];
    const int*   pos = (const int*)  d_in[1];
    const float* Wq  = (const float*)d_in[2];
    const float* Wk  = (const float*)d_in[3];
    const float* Wv  = (const float*)d_in[4];
    const float* Wo  = (const float*)d_in[5];
    float* out = (float*)d_out;

    cudaFuncSetAttribute(mm_qkv_kernel, cudaFuncAttributeMaxDynamicSharedMemorySize, MM_SMEM);
    cudaFuncSetAttribute(mm_out_kernel, cudaFuncAttributeMaxDynamicSharedMemorySize, MO_SMEM);
    cudaFuncSetAttribute(attn_kernel, cudaFuncAttributeMaxDynamicSharedMemorySize, AT_SMEM);

    prep_kernel<<<(S * D) / 1024, 256>>>(x, pos, Wq, Wk, Wv, Wo);

    mm_qkv_kernel<<<dim3(D / 128, S / 128, 3), 128, MM_SMEM>>>();
    attn_kernel<<<dim3(S / 64, H), 128, AT_SMEM>>>();
    mm_out_kernel<<<dim3(D / 128, S / 64), 128, MO_SMEM>>>(out);
}